// round 10
// baseline (speedup 1.0000x reference)
#include <cuda_runtime.h>
#include <cuda_bf16.h>
#include <cstdint>

#define Bn   64
#define Tn   512
#define Hn   32
#define REDn 128
#define DC   4096
#define DD   512
#define DM   256
#define DT   4864
#define Mrows (Bn*Tn)   // 32768

#define KT    32              // bf16 K per tile
#define NKT   (DT/KT)         // 152 k-tiles
#define MT    256             // M rows per CTA

// -------- scratch (static __device__, no allocations) --------
__device__ float g_xg[(size_t)Mrows * 192];               // 24 MB
__device__ float g_outF[(size_t)Mrows * Hn];              // 4 MB
__device__ float g_outB[(size_t)Mrows * Hn];              // 4 MB
__device__ __nv_bfloat16 g_Whi[(size_t)REDn * DT];        // 1.25 MB
__device__ __nv_bfloat16 g_Wlo[(size_t)REDn * DT];        // 1.25 MB

// ============================================================
// helpers
// ============================================================
__device__ __forceinline__ uint32_t smem_u32(const void* p) {
    uint32_t a;
    asm("{ .reg .u64 t; cvta.to.shared.u64 t, %1; cvt.u32.u64 %0, t; }" : "=r"(a) : "l"(p));
    return a;
}
__device__ __forceinline__ void cp16(uint32_t dst, const void* src) {
    asm volatile("cp.async.cg.shared.global [%0], [%1], 16;" :: "r"(dst), "l"(src) : "memory");
}
__device__ __forceinline__ void cp_commit() {
    asm volatile("cp.async.commit_group;" ::: "memory");
}
__device__ __forceinline__ void cp_wait1() {
    asm volatile("cp.async.wait_group 1;" ::: "memory");
}
__device__ __forceinline__ void cp_wait0() {
    asm volatile("cp.async.wait_group 0;" ::: "memory");
}
__device__ __forceinline__ void ldsm_x4(uint32_t* r, uint32_t addr) {
    asm volatile("ldmatrix.sync.aligned.m8n8.x4.shared.b16 {%0,%1,%2,%3}, [%4];"
                 : "=r"(r[0]), "=r"(r[1]), "=r"(r[2]), "=r"(r[3]) : "r"(addr));
}
__device__ __forceinline__ void mma16816(float* c, const uint32_t* a, const uint32_t* b) {
    asm volatile("mma.sync.aligned.m16n8k16.row.col.f32.bf16.bf16.f32 "
                 "{%0,%1,%2,%3}, {%4,%5,%6,%7}, {%8,%9}, {%0,%1,%2,%3};"
                 : "+f"(c[0]), "+f"(c[1]), "+f"(c[2]), "+f"(c[3])
                 : "r"(a[0]), "r"(a[1]), "r"(a[2]), "r"(a[3]), "r"(b[0]), "r"(b[1]));
}
__device__ __forceinline__ void split4(float4 v, uint32_t& h01, uint32_t& h23,
                                       uint32_t& l01, uint32_t& l23) {
    __nv_bfloat16 h0 = __float2bfloat16_rn(v.x);
    __nv_bfloat16 h1 = __float2bfloat16_rn(v.y);
    __nv_bfloat16 h2 = __float2bfloat16_rn(v.z);
    __nv_bfloat16 h3 = __float2bfloat16_rn(v.w);
    float r0 = v.x - __bfloat162float(h0);
    float r1 = v.y - __bfloat162float(h1);
    float r2 = v.z - __bfloat162float(h2);
    float r3 = v.w - __bfloat162float(h3);
    __nv_bfloat162 H0 = __halves2bfloat162(h0, h1);
    __nv_bfloat162 H1 = __halves2bfloat162(h2, h3);
    __nv_bfloat162 L0 = __floats2bfloat162_rn(r0, r1);
    __nv_bfloat162 L1 = __floats2bfloat162_rn(r2, r3);
    h01 = *reinterpret_cast<uint32_t*>(&H0);
    h23 = *reinterpret_cast<uint32_t*>(&H1);
    l01 = *reinterpret_cast<uint32_t*>(&L0);
    l23 = *reinterpret_cast<uint32_t*>(&L1);
}
// packed dual-fp32 ops
__device__ __forceinline__ unsigned long long pack2(float x, float y) {
    unsigned long long r;
    asm("mov.b64 %0, {%1,%2};" : "=l"(r) : "f"(x), "f"(y));
    return r;
}
__device__ __forceinline__ unsigned long long ffma2(unsigned long long a,
                                                    unsigned long long b,
                                                    unsigned long long c) {
    unsigned long long d;
    asm("fma.rn.f32x2 %0, %1, %2, %3;" : "=l"(d) : "l"(a), "l"(b), "l"(c));
    return d;
}
__device__ __forceinline__ unsigned long long fadd2(unsigned long long a,
                                                    unsigned long long b) {
    unsigned long long d;
    asm("add.rn.f32x2 %0, %1, %2;" : "=l"(d) : "l"(a), "l"(b));
    return d;
}
__device__ __forceinline__ float2 unpack2(unsigned long long v) {
    float2 f;
    asm("mov.b64 {%0,%1}, %2;" : "=f"(f.x), "=f"(f.y) : "l"(v));
    return f;
}
__device__ __forceinline__ float rcp_fast(float x) {
    float y;
    asm("rcp.approx.f32 %0, %1;" : "=f"(y) : "f"(x));
    return y;
}
__device__ __forceinline__ float sigmoid_fast(float x) {
    return rcp_fast(1.f + __expf(-x));
}
__device__ __forceinline__ float tanh_fast(float x) {
    return __fmaf_rn(2.f, rcp_fast(1.f + __expf(-2.f * x)), -1.f);
}

// ============================================================
// Kernel 0: split fc0_w into bf16 hi/lo
// ============================================================
__global__ void __launch_bounds__(256) k_prep_w(const float* __restrict__ W) {
    int i = blockIdx.x * 256 + threadIdx.x;
    if (i < REDn * DT) {
        float x = W[i];
        __nv_bfloat16 h = __float2bfloat16_rn(x);
        g_Whi[i] = h;
        g_Wlo[i] = __float2bfloat16_rn(x - __bfloat162float(h));
    }
}

// ============================================================
// Kernel 1: FUSED split-bf16 GEMM1 + GEMM2.
// Mainloop: scores_tile[256,128] = concat(...) @ fc0_w^T (mma.sync, 3 terms)
// Epilogue: scores+bias -> smem; xg[256,192] = scores @ [wih_f;wih_b]^T + bih
//           computed with packed f32x2 FMAs; g_scores never touches HBM.
// MT=256, 16 warps (4m x 4n), warp tile 64x32, 3-stage ring, early exit.
//
// SMEM (1024-aligned base), mainloop:
//   [0     :20480)  A_hi bf16 [256 x 80B pad]
//   [20480 :40960)  A_lo
//   ring stage s at 40960 + s*53248: A fp32 staging 32KB | W_hi 10240 | W_lo 10240
// SMEM, epilogue (reuses everything):
//   [0      :135168)  ssc fp32 [256][132]
//   [135168 :186624)  wsm fp32 [96][134]
// ============================================================
#define SM_ABF_HI 0u
#define SM_ABF_LO 20480u
#define SM_RING   40960u
#define STG       53248u
#define STG_W_HI  32768u
#define STG_W_LO  43008u
#define DYN_SMEM  (40960 + 3*53248 + 1024)   // 201728

__global__ void __launch_bounds__(512, 1) k_gemm_fused(
    const float* __restrict__ content, const float* __restrict__ distort,
    const float* __restrict__ motion,  const float* __restrict__ bias,
    const float* __restrict__ wih_f,   const float* __restrict__ wih_b,
    const float* __restrict__ bih_f,   const float* __restrict__ bih_b,
    const int* __restrict__ inputLength)
{
    const int m0 = blockIdx.x * MT;
    {   // early exit: tile rows all >= vlen of this batch
        const int vlen = inputLength[m0 >> 9] - 9;
        if ((m0 & 511) >= vlen) return;
    }

    extern __shared__ char dynsmem[];
    __shared__ float s_bias[128];

    const int tid = threadIdx.x;
    const int wid = tid >> 5;
    const int lid = tid & 31;
    const int wm  = wid & 3;     // 4 m-warps x 64 rows
    const int wn  = wid >> 2;    // 4 n-warps x 32 cols

    const uint32_t raw  = smem_u32(dynsmem);
    const uint32_t base = (raw + 1023u) & ~1023u;
    char* sm = dynsmem + (base - raw);

    if (tid < 128) s_bias[tid] = bias[tid];

    const int hrow = tid >> 2;   // W row 0..127
    const int jw   = tid & 3;

    const uint32_t aoff = (uint32_t)((wm * 64 + (lid & 15)) * 80 + ((lid >> 4) << 4));
    const int g3 = lid >> 3;
    const uint32_t brow_off = (uint32_t)(((g3 >> 1) << 3) + (lid & 7));
    const uint32_t bk_off   = (uint32_t)((g3 & 1) * 16);

    float acc[4][4][4];
#pragma unroll
    for (int i = 0; i < 4; i++)
#pragma unroll
        for (int j = 0; j < 4; j++)
#pragma unroll
            for (int k = 0; k < 4; k++) acc[i][j][k] = 0.f;

    auto issue_tile = [&](int c) {
        if (c < NKT) {
            const int kt = c * KT;
            const uint32_t sb = base + SM_RING + (uint32_t)(c % 3) * STG;
            const float* asrc; int astr, koff;
            if (kt < DC)           { asrc = content; astr = DC; koff = kt; }
            else if (kt < DC + DD) { asrc = distort; astr = DD; koff = kt - DC; }
            else                   { asrc = motion;  astr = DM; koff = kt - DC - DD; }
#pragma unroll
            for (int i = 0; i < 4; ++i) {
                int chunk = i * 512 + tid;          // 2048 = 256 rows x 8 chunks
                int r   = chunk >> 3;
                int c16 = chunk & 7;
                cp16(sb + (uint32_t)(r * 128 + c16 * 16),
                     asrc + (size_t)(m0 + r) * astr + koff + c16 * 4);
            }
            cp16(sb + STG_W_HI + (uint32_t)(hrow * 80 + jw * 16),
                 (const char*)g_Whi + ((size_t)hrow * DT + kt) * 2 + jw * 16);
            cp16(sb + STG_W_LO + (uint32_t)(hrow * 80 + jw * 16),
                 (const char*)g_Wlo + ((size_t)hrow * DT + kt) * 2 + jw * 16);
        }
        cp_commit();
    };

    issue_tile(0);
    issue_tile(1);

    for (int c = 0; c < NKT; ++c) {
        const uint32_t sb = base + SM_RING + (uint32_t)(c % 3) * STG;
        cp_wait1();
        __syncthreads();

        // convert A fp32 staging -> A_hi / A_lo bf16 (padded rows)
#pragma unroll
        for (int i = 0; i < 4; ++i) {
            int chunk = i * 512 + tid;
            int r = chunk >> 3;
            int j = chunk & 7;
            float4 v = *reinterpret_cast<const float4*>(
                sm + (sb - base) + (uint32_t)(r * 128 + j * 16));
            uint32_t h01, h23, l01, l23;
            split4(v, h01, h23, l01, l23);
            *reinterpret_cast<uint2*>(sm + SM_ABF_HI + r * 80 + j * 8) = make_uint2(h01, h23);
            *reinterpret_cast<uint2*>(sm + SM_ABF_LO + r * 80 + j * 8) = make_uint2(l01, l23);
        }
        __syncthreads();

        issue_tile(c + 2);

        const uint32_t wbh = sb + STG_W_HI;
#pragma unroll
        for (int ks = 0; ks < 2; ks++) {
            const uint32_t akb = base + SM_ABF_HI + aoff + (uint32_t)(ks * 32);
            uint32_t ah[4][4], al[4][4], bb[4][2];
#pragma unroll
            for (int mf = 0; mf < 4; mf++) ldsm_x4(ah[mf], akb + (uint32_t)(mf * 1280));
#pragma unroll
            for (int p = 0; p < 2; p++) {
                uint32_t r4[4];
                uint32_t addr = wbh + (uint32_t)((wn * 32 + p * 16 + brow_off) * 80)
                                    + bk_off + (uint32_t)(ks * 32);
                ldsm_x4(r4, addr);
                bb[2*p][0] = r4[0]; bb[2*p][1] = r4[1];
                bb[2*p+1][0] = r4[2]; bb[2*p+1][1] = r4[3];
            }
#pragma unroll
            for (int mf = 0; mf < 4; mf++)
#pragma unroll
                for (int nf = 0; nf < 4; nf++) mma16816(acc[mf][nf], ah[mf], bb[nf]);
#pragma unroll
            for (int mf = 0; mf < 4; mf++) ldsm_x4(al[mf], akb + 20480u + (uint32_t)(mf * 1280));
#pragma unroll
            for (int mf = 0; mf < 4; mf++)
#pragma unroll
                for (int nf = 0; nf < 4; nf++) mma16816(acc[mf][nf], al[mf], bb[nf]);
#pragma unroll
            for (int p = 0; p < 2; p++) {
                uint32_t r4[4];
                uint32_t addr = wbh + 10240u + (uint32_t)((wn * 32 + p * 16 + brow_off) * 80)
                                    + bk_off + (uint32_t)(ks * 32);
                ldsm_x4(r4, addr);
                bb[2*p][0] = r4[0]; bb[2*p][1] = r4[1];
                bb[2*p+1][0] = r4[2]; bb[2*p+1][1] = r4[3];
            }
#pragma unroll
            for (int mf = 0; mf < 4; mf++)
#pragma unroll
                for (int nf = 0; nf < 4; nf++) mma16816(acc[mf][nf], ah[mf], bb[nf]);
        }
    }

    // ================= fused epilogue: xg = (scores+b0) @ wih^T + bih ==========
    cp_wait0();
    __syncthreads();   // ring smem now free for reuse

    float* ssc = reinterpret_cast<float*>(sm);            // [256][132]
    {
        const int gq = lid >> 2;
        const int t4 = lid & 3;
#pragma unroll
        for (int mf = 0; mf < 4; mf++) {
            const int r0 = wm * 64 + mf * 16 + gq;
#pragma unroll
            for (int nf = 0; nf < 4; nf++) {
                const int col = wn * 32 + nf * 8 + 2 * t4;
                const float b0 = s_bias[col], b1 = s_bias[col + 1];
                ssc[r0 * 132 + col]           = acc[mf][nf][0] + b0;
                ssc[r0 * 132 + col + 1]       = acc[mf][nf][1] + b1;
                ssc[(r0 + 8) * 132 + col]     = acc[mf][nf][2] + b0;
                ssc[(r0 + 8) * 132 + col + 1] = acc[mf][nf][3] + b1;
            }
        }
    }
    __syncthreads();

    float* wsm = reinterpret_cast<float*>(sm + 135168);   // [96][134]
    const int rg  = tid >> 4;    // 0..31 -> rows rg*8..rg*8+7
    const int cgl = tid & 15;    // 0..15 -> cols cgl*6..cgl*6+5 (within chunk)
    const int cb  = cgl * 6;

#pragma unroll
    for (int ch = 0; ch < 2; ++ch) {
        const float* wsrc = ch ? wih_b : wih_f;   // 96 rows x 128
        // load W chunk as float2: 96*64 = 6144 f2, 12 per thread
#pragma unroll
        for (int i = 0; i < 12; ++i) {
            int idx = i * 512 + tid;
            int r   = idx >> 6;
            int c2  = idx & 63;
            float2 v = *reinterpret_cast<const float2*>(wsrc + r * REDn + c2 * 2);
            *reinterpret_cast<float2*>(wsm + r * 134 + c2 * 2) = v;
        }
        __syncthreads();

        const float* bsrc = ch ? bih_b : bih_f;
        float bv[6];
#pragma unroll
        for (int cc = 0; cc < 6; cc++) bv[cc] = bsrc[cb + cc];

#pragma unroll
        for (int p = 0; p < 2; ++p) {
            const int rbase = rg * 8 + p * 4;
            unsigned long long accp[4][6];
#pragma unroll
            for (int i = 0; i < 4; i++)
#pragma unroll
                for (int cc = 0; cc < 6; cc++) accp[i][cc] = 0ull;

            for (int kp = 0; kp < 64; ++kp) {
                unsigned long long sv[4], wv[6];
#pragma unroll
                for (int i = 0; i < 4; i++)
                    sv[i] = *reinterpret_cast<const unsigned long long*>(
                        &ssc[(rbase + i) * 132 + 2 * kp]);
#pragma unroll
                for (int cc = 0; cc < 6; cc++)
                    wv[cc] = *reinterpret_cast<const unsigned long long*>(
                        &wsm[(cb + cc) * 134 + 2 * kp]);
#pragma unroll
                for (int i = 0; i < 4; i++)
#pragma unroll
                    for (int cc = 0; cc < 6; cc++)
                        accp[i][cc] = ffma2(sv[i], wv[cc], accp[i][cc]);
            }
#pragma unroll
            for (int i = 0; i < 4; ++i) {
                const int grow = m0 + rbase + i;
                float o[6];
#pragma unroll
                for (int cc = 0; cc < 6; cc++) {
                    float2 f = unpack2(accp[i][cc]);
                    o[cc] = f.x + f.y + bv[cc];
                }
                float* dst = g_xg + (size_t)grow * 192 + ch * 96 + cb;
                *reinterpret_cast<float2*>(dst)     = make_float2(o[0], o[1]);
                *reinterpret_cast<float2*>(dst + 2) = make_float2(o[2], o[3]);
                *reinterpret_cast<float2*>(dst + 4) = make_float2(o[4], o[5]);
            }
        }
        __syncthreads();   // before next chunk overwrites wsm
    }
}

// ============================================================
// Kernel 3: masked GRU — one warp per (batch, direction), loop to vlen.
// True prefetch depth 6 (register ring, unroll x6); rcp.approx activations.
// ============================================================
__global__ void __launch_bounds__(32) k_gru(
    const int*   __restrict__ inputLength,
    const float* __restrict__ whh_f, const float* __restrict__ whh_b,
    const float* __restrict__ bhh_f, const float* __restrict__ bhh_b)
{
    const int b   = blockIdx.x;
    const int dir = blockIdx.y;
    const int j   = threadIdx.x;   // 0..31

    const float* whh = dir ? whh_b : whh_f;
    const float* bhh = dir ? bhh_b : bhh_f;

    unsigned long long wr[16], wz[16], wn2[16];
    const float2* wrp = reinterpret_cast<const float2*>(whh + j * 32);
    const float2* wzp = reinterpret_cast<const float2*>(whh + (32 + j) * 32);
    const float2* wnp = reinterpret_cast<const float2*>(whh + (64 + j) * 32);
#pragma unroll
    for (int i = 0; i < 16; i++) {
        float2 a = wrp[i], cz = wzp[i], d = wnp[i];
        wr[i]  = pack2(a.x, a.y);
        wz[i]  = pack2(cz.x, cz.y);
        wn2[i] = pack2(d.x, d.y);
    }
    const float br = bhh[j], bz = bhh[32 + j], bn = bhh[64 + j];

    __shared__ __align__(16) float sh[2][32];

    const int vlen = inputLength[b] - 9;   // >= 191
    float* outp = (dir ? g_outB : g_outF) + (size_t)b * Tn * Hn + j;
    const float* xgbase = g_xg + (size_t)b * Tn * 192 + dir * 96;

    // register ring: 6 sets (vlen >= 191 >> 6, all preloads valid)
    float xr0,xz0,xn0, xr1,xz1,xn1, xr2,xz2,xn2, xr3,xz3,xn3, xr4,xz4,xn4, xr5,xz5,xn5;
#define PRELOAD(K, XR, XZ, XN)                                                \
    {                                                                         \
        const float* x = xgbase + (size_t)(dir ? (vlen - 1 - (K)) : (K)) * 192; \
        XR = x[j]; XZ = x[32 + j]; XN = x[64 + j];                            \
    }
    PRELOAD(0, xr0, xz0, xn0)
    PRELOAD(1, xr1, xz1, xn1)
    PRELOAD(2, xr2, xz2, xn2)
    PRELOAD(3, xr3, xz3, xn3)
    PRELOAD(4, xr4, xz4, xn4)
    PRELOAD(5, xr5, xz5, xn5)
#undef PRELOAD

    float h = 0.f;
    int s = 0;

#define GRU_STEP(XR, XZ, XN)                                                  \
    {                                                                         \
        const float cxr = XR, cxz = XZ, cxn = XN;                             \
        const int sp = s + 6;                                                 \
        if (sp < vlen) {                                                      \
            const float* x = xgbase + (size_t)(dir ? (vlen - 1 - sp) : sp) * 192; \
            XR = x[j]; XZ = x[32 + j]; XN = x[64 + j];                        \
        }                                                                     \
        sh[s & 1][j] = h;                                                     \
        __syncwarp();                                                         \
        const unsigned long long* hp =                                        \
            reinterpret_cast<const unsigned long long*>(&sh[s & 1][0]);       \
        unsigned long long ar0 = 0ull, ar1 = 0ull;                            \
        unsigned long long az0 = 0ull, az1 = 0ull;                            \
        unsigned long long an0 = 0ull, an1 = 0ull;                            \
        _Pragma("unroll")                                                     \
        for (int i = 0; i < 16; i += 2) {                                     \
            unsigned long long hv0 = hp[i];                                   \
            unsigned long long hv1 = hp[i + 1];                               \
            ar0 = ffma2(hv0, wr[i],      ar0);                                \
            ar1 = ffma2(hv1, wr[i + 1],  ar1);                                \
            az0 = ffma2(hv0, wz[i],      az0);                                \
            az1 = ffma2(hv1, wz[i + 1],  az1);                                \
            an0 = ffma2(hv0, wn2[i],     an0);                                \
            an1 = ffma2(hv1, wn2[i + 1], an1);                                \
        }                                                                     \
        float2 fr = unpack2(fadd2(ar0, ar1));                                 \
        float2 fz = unpack2(fadd2(az0, az1));                                 \
        float2 fn = unpack2(fadd2(an0, an1));                                 \
        float hgr = fr.x + fr.y + br;                                         \
        float hgz = fz.x + fz.y + bz;                                         \
        float hgn = fn.x + fn.y + bn;                                         \
        float r  = sigmoid_fast(cxr + hgr);                                   \
        float z  = sigmoid_fast(cxz + hgz);                                   \
        float nn = tanh_fast(__fmaf_rn(r, hgn, cxn));                         \
        h = __fmaf_rn(z, h - nn, nn);                                         \
        int tout = dir ? (vlen - 1 - s) : s;                                  \
        outp[(size_t)tout * Hn] = h;                                          \
        s++;                                                                  \
    }

    while (s + 6 <= vlen) {
        GRU_STEP(xr0, xz0, xn0)
        GRU_STEP(xr1, xz1, xn1)
        GRU_STEP(xr2, xz2, xn2)
        GRU_STEP(xr3, xz3, xn3)
        GRU_STEP(xr4, xz4, xn4)
        GRU_STEP(xr5, xz5, xn5)
    }
    if (s < vlen) GRU_STEP(xr0, xz0, xn0)
    if (s < vlen) GRU_STEP(xr1, xz1, xn1)
    if (s < vlen) GRU_STEP(xr2, xz2, xn2)
    if (s < vlen) GRU_STEP(xr3, xz3, xn3)
    if (s < vlen) GRU_STEP(xr4, xz4, xn4)
#undef GRU_STEP
}

// ============================================================
// Kernel 4: q projection + MLP + argmax-selected TP score.
// ============================================================
__global__ void __launch_bounds__(512) k_final(
    const int*   __restrict__ inputLength,
    const float* __restrict__ qw,  const float* __restrict__ qb,
    const float* __restrict__ m1w, const float* __restrict__ m1b,
    const float* __restrict__ m2w, const float* __restrict__ m2b,
    float* __restrict__ out)
{
    const int b = blockIdx.x;
    const int t = threadIdx.x;
    __shared__ float sq[512];
    __shared__ float sh1[32];
    __shared__ int   s_tau;
    __shared__ float wsum[16];

    const int vlen = inputLength[b] - 9;

    float qv = 0.f;
    if (t < vlen) {
        const float* of = g_outF + ((size_t)b * Tn + t) * Hn;
        const float* ob = g_outB + ((size_t)b * Tn + t) * Hn;
        float a = qb[0];
#pragma unroll
        for (int jj = 0; jj < 32; jj++) a += of[jj] * qw[jj] + ob[jj] * qw[32 + jj];
        qv = a;
    }
    sq[t] = qv;
    __syncthreads();

    if (t < 32) {
        const float* lf = g_outF + ((size_t)b * Tn + (vlen - 1)) * Hn;
        const float* lb = g_outB + ((size_t)b * Tn) * Hn;
        float a = m1b[t];
#pragma unroll
        for (int jj = 0; jj < 32; jj++) a += lf[jj] * m1w[t * 64 + jj] + lb[jj] * m1w[t * 64 + 32 + jj];
        sh1[t] = fmaxf(a, 0.f);
    }
    __syncthreads();
    if (t == 0) {
        float best = -3.0e38f; int bi = 0;
#pragma unroll
        for (int c = 0; c < 5; c++) {
            float v = m2b[c];
#pragma unroll
            for (int o = 0; o < 32; o++) v += sh1[o] * m2w[c * 32 + o];
            if (v > best) { best = v; bi = c; }
        }
        s_tau = 8 + 2 * bi;
    }
    __syncthreads();

    const int tau = s_tau;
    float pm = 0.f;
    if (t < vlen) {
        float l = 3.0e38f;
        for (int k = 0; k < tau; k++) {
            int idx = t - k;
            float v = (idx >= 0) ? sq[idx] : 3.0e38f;
            l = fminf(l, v);
        }
        float msum = 0.f, nsum = 0.f;
        for (int k = 0; k < tau; k++) {
            int idx = t + k;
            if (idx < vlen) {
                float w = __expf(-sq[idx]);
                nsum += w;
                msum += sq[idx] * w;
            }
        }
        float ratio = (nsum > 0.f) ? (msum / nsum) : 0.f;
        pm = 0.5f * (ratio + l);
    }
    float v = pm;
#pragma unroll
    for (int o = 16; o > 0; o >>= 1) v += __shfl_down_sync(0xffffffffu, v, o);
    if ((t & 31) == 0) wsum[t >> 5] = v;
    __syncthreads();
    if (t == 0) {
        float s = 0.f;
#pragma unroll
        for (int w = 0; w < 16; w++) s += wsum[w];
        out[b] = s / (float)vlen;
    }
}

// ============================================================
extern "C" void kernel_launch(void* const* d_in, const int* in_sizes, int n_in,
                              void* d_out, int out_size) {
    (void)in_sizes; (void)n_in; (void)out_size;
    const float* motion   = (const float*)d_in[0];
    const float* content  = (const float*)d_in[1];
    const float* distort  = (const float*)d_in[2];
    const int*   inlen    = (const int*)  d_in[3];
    const float* fc0w     = (const float*)d_in[4];
    const float* fc0b     = (const float*)d_in[5];
    const float* wih_f    = (const float*)d_in[6];
    const float* whh_f    = (const float*)d_in[7];
    const float* bih_f    = (const float*)d_in[8];
    const float* bhh_f    = (const float*)d_in[9];
    const float* wih_b    = (const float*)d_in[10];
    const float* whh_b    = (const float*)d_in[11];
    const float* bih_b    = (const float*)d_in[12];
    const float* bhh_b    = (const float*)d_in[13];
    const float* qw       = (const float*)d_in[14];
    const float* qb       = (const float*)d_in[15];
    const float* m1w      = (const float*)d_in[16];
    const float* m1b      = (const float*)d_in[17];
    const float* m2w      = (const float*)d_in[18];
    const float* m2b      = (const float*)d_in[19];
    float* out = (float*)d_out;

    cudaFuncSetAttribute(k_gemm_fused, cudaFuncAttributeMaxDynamicSharedMemorySize, DYN_SMEM);

    k_prep_w<<<(REDn * DT + 255) / 256, 256>>>(fc0w);
    k_gemm_fused<<<Mrows / MT, 512, DYN_SMEM>>>(content, distort, motion, fc0b,
                                                wih_f, wih_b, bih_f, bih_b, inlen);
    k_gru<<<dim3(Bn, 2), 32>>>(inlen, whh_f, whh_b, bhh_f, bhh_b);
    k_final<<<Bn, 512>>>(inlen, qw, qb, m1w, m1b, m2w, m2b, out);
}

// round 11
// speedup vs baseline: 1.0695x; 1.0695x over previous
#include <cuda_runtime.h>
#include <cuda_bf16.h>
#include <cstdint>

#define Bn   64
#define Tn   512
#define Hn   32
#define REDn 128
#define DC   4096
#define DD   512
#define DM   256
#define DT   4864
#define Mrows (Bn*Tn)   // 32768

#define KT    32              // bf16 K per tile
#define NKT   (DT/KT)         // 152 k-tiles
#define MT    256             // M rows per CTA

// -------- scratch (static __device__, no allocations) --------
__device__ float g_scores[(size_t)Mrows * REDn];          // 16 MB
__device__ float g_xg[(size_t)Mrows * 192];               // 24 MB
__device__ float g_outF[(size_t)Mrows * Hn];              // 4 MB
__device__ float g_outB[(size_t)Mrows * Hn];              // 4 MB
__device__ __nv_bfloat16 g_Whi[(size_t)REDn * DT];        // 1.25 MB
__device__ __nv_bfloat16 g_Wlo[(size_t)REDn * DT];        // 1.25 MB

// ============================================================
// helpers
// ============================================================
__device__ __forceinline__ uint32_t smem_u32(const void* p) {
    uint32_t a;
    asm("{ .reg .u64 t; cvta.to.shared.u64 t, %1; cvt.u32.u64 %0, t; }" : "=r"(a) : "l"(p));
    return a;
}
__device__ __forceinline__ void cp16(uint32_t dst, const void* src) {
    asm volatile("cp.async.cg.shared.global [%0], [%1], 16;" :: "r"(dst), "l"(src) : "memory");
}
__device__ __forceinline__ void cp_commit() {
    asm volatile("cp.async.commit_group;" ::: "memory");
}
__device__ __forceinline__ void cp_wait1() {
    asm volatile("cp.async.wait_group 1;" ::: "memory");
}
__device__ __forceinline__ void ldsm_x4(uint32_t* r, uint32_t addr) {
    asm volatile("ldmatrix.sync.aligned.m8n8.x4.shared.b16 {%0,%1,%2,%3}, [%4];"
                 : "=r"(r[0]), "=r"(r[1]), "=r"(r[2]), "=r"(r[3]) : "r"(addr));
}
__device__ __forceinline__ void mma16816(float* c, const uint32_t* a, const uint32_t* b) {
    asm volatile("mma.sync.aligned.m16n8k16.row.col.f32.bf16.bf16.f32 "
                 "{%0,%1,%2,%3}, {%4,%5,%6,%7}, {%8,%9}, {%0,%1,%2,%3};"
                 : "+f"(c[0]), "+f"(c[1]), "+f"(c[2]), "+f"(c[3])
                 : "r"(a[0]), "r"(a[1]), "r"(a[2]), "r"(a[3]), "r"(b[0]), "r"(b[1]));
}
__device__ __forceinline__ void split4(float4 v, uint32_t& h01, uint32_t& h23,
                                       uint32_t& l01, uint32_t& l23) {
    __nv_bfloat16 h0 = __float2bfloat16_rn(v.x);
    __nv_bfloat16 h1 = __float2bfloat16_rn(v.y);
    __nv_bfloat16 h2 = __float2bfloat16_rn(v.z);
    __nv_bfloat16 h3 = __float2bfloat16_rn(v.w);
    float r0 = v.x - __bfloat162float(h0);
    float r1 = v.y - __bfloat162float(h1);
    float r2 = v.z - __bfloat162float(h2);
    float r3 = v.w - __bfloat162float(h3);
    __nv_bfloat162 H0 = __halves2bfloat162(h0, h1);
    __nv_bfloat162 H1 = __halves2bfloat162(h2, h3);
    __nv_bfloat162 L0 = __floats2bfloat162_rn(r0, r1);
    __nv_bfloat162 L1 = __floats2bfloat162_rn(r2, r3);
    h01 = *reinterpret_cast<uint32_t*>(&H0);
    h23 = *reinterpret_cast<uint32_t*>(&H1);
    l01 = *reinterpret_cast<uint32_t*>(&L0);
    l23 = *reinterpret_cast<uint32_t*>(&L1);
}
// packed dual-fp32 ops
__device__ __forceinline__ unsigned long long pack2(float x, float y) {
    unsigned long long r;
    asm("mov.b64 %0, {%1,%2};" : "=l"(r) : "f"(x), "f"(y));
    return r;
}
__device__ __forceinline__ unsigned long long ffma2(unsigned long long a,
                                                    unsigned long long b,
                                                    unsigned long long c) {
    unsigned long long d;
    asm("fma.rn.f32x2 %0, %1, %2, %3;" : "=l"(d) : "l"(a), "l"(b), "l"(c));
    return d;
}
__device__ __forceinline__ unsigned long long fadd2(unsigned long long a,
                                                    unsigned long long b) {
    unsigned long long d;
    asm("add.rn.f32x2 %0, %1, %2;" : "=l"(d) : "l"(a), "l"(b));
    return d;
}
__device__ __forceinline__ float2 unpack2(unsigned long long v) {
    float2 f;
    asm("mov.b64 {%0,%1}, %2;" : "=f"(f.x), "=f"(f.y) : "l"(v));
    return f;
}
__device__ __forceinline__ float rcp_fast(float x) {
    float y;
    asm("rcp.approx.f32 %0, %1;" : "=f"(y) : "f"(x));
    return y;
}
__device__ __forceinline__ float sigmoid_fast(float x) {
    return rcp_fast(1.f + __expf(-x));
}
__device__ __forceinline__ float tanh_fast(float x) {
    return __fmaf_rn(2.f, rcp_fast(1.f + __expf(-2.f * x)), -1.f);
}

// ============================================================
// Kernel 0: split fc0_w into bf16 hi/lo
// ============================================================
__global__ void __launch_bounds__(256) k_prep_w(const float* __restrict__ W) {
    int i = blockIdx.x * 256 + threadIdx.x;
    if (i < REDn * DT) {
        float x = W[i];
        __nv_bfloat16 h = __float2bfloat16_rn(x);
        g_Whi[i] = h;
        g_Wlo[i] = __float2bfloat16_rn(x - __bfloat162float(h));
    }
}

// ============================================================
// Kernel 1: mma.sync split-bf16 GEMM, MT=256, 16 warps (4m x 4n),
// warp tile 64x32. 3-stage ring, 2 syncs/tile. Early exit at
// 256-row granularity. (R9 measured-best configuration.)
// ============================================================
#define SM_ABF_HI 0u
#define SM_ABF_LO 20480u
#define SM_RING   40960u
#define STG       53248u
#define STG_W_HI  32768u
#define STG_W_LO  43008u
#define DYN_SMEM  (40960 + 3*53248 + 1024)   // 201728

__global__ void __launch_bounds__(512, 1) k_gemm1_mma(
    const float* __restrict__ content, const float* __restrict__ distort,
    const float* __restrict__ motion,  const float* __restrict__ bias,
    const int* __restrict__ inputLength)
{
    const int m0 = blockIdx.x * MT;
    {   // early exit: tile rows all >= vlen of this batch
        const int vlen = inputLength[m0 >> 9] - 9;
        if ((m0 & 511) >= vlen) return;
    }

    extern __shared__ char dynsmem[];
    __shared__ float s_bias[128];

    const int tid = threadIdx.x;
    const int wid = tid >> 5;
    const int lid = tid & 31;
    const int wm  = wid & 3;     // 4 m-warps x 64 rows
    const int wn  = wid >> 2;    // 4 n-warps x 32 cols

    const uint32_t raw  = smem_u32(dynsmem);
    const uint32_t base = (raw + 1023u) & ~1023u;
    char* sm = dynsmem + (base - raw);

    if (tid < 128) s_bias[tid] = bias[tid];

    const int hrow = tid >> 2;
    const int jw   = tid & 3;

    const uint32_t aoff = (uint32_t)((wm * 64 + (lid & 15)) * 80 + ((lid >> 4) << 4));
    const int g3 = lid >> 3;
    const uint32_t brow_off = (uint32_t)(((g3 >> 1) << 3) + (lid & 7));
    const uint32_t bk_off   = (uint32_t)((g3 & 1) * 16);

    float acc[4][4][4];
#pragma unroll
    for (int i = 0; i < 4; i++)
#pragma unroll
        for (int j = 0; j < 4; j++)
#pragma unroll
            for (int k = 0; k < 4; k++) acc[i][j][k] = 0.f;

    auto issue_tile = [&](int c) {
        if (c < NKT) {
            const int kt = c * KT;
            const uint32_t sb = base + SM_RING + (uint32_t)(c % 3) * STG;
            const float* asrc; int astr, koff;
            if (kt < DC)           { asrc = content; astr = DC; koff = kt; }
            else if (kt < DC + DD) { asrc = distort; astr = DD; koff = kt - DC; }
            else                   { asrc = motion;  astr = DM; koff = kt - DC - DD; }
#pragma unroll
            for (int i = 0; i < 4; ++i) {
                int chunk = i * 512 + tid;          // 2048 = 256 rows x 8 chunks
                int r   = chunk >> 3;
                int c16 = chunk & 7;
                cp16(sb + (uint32_t)(r * 128 + c16 * 16),
                     asrc + (size_t)(m0 + r) * astr + koff + c16 * 4);
            }
            cp16(sb + STG_W_HI + (uint32_t)(hrow * 80 + jw * 16),
                 (const char*)g_Whi + ((size_t)hrow * DT + kt) * 2 + jw * 16);
            cp16(sb + STG_W_LO + (uint32_t)(hrow * 80 + jw * 16),
                 (const char*)g_Wlo + ((size_t)hrow * DT + kt) * 2 + jw * 16);
        }
        cp_commit();
    };

    issue_tile(0);
    issue_tile(1);

    for (int c = 0; c < NKT; ++c) {
        const uint32_t sb = base + SM_RING + (uint32_t)(c % 3) * STG;
        cp_wait1();
        __syncthreads();

        // convert A fp32 staging -> A_hi / A_lo bf16 (padded rows)
#pragma unroll
        for (int i = 0; i < 4; ++i) {
            int chunk = i * 512 + tid;
            int r = chunk >> 3;
            int j = chunk & 7;
            float4 v = *reinterpret_cast<const float4*>(
                sm + (sb - base) + (uint32_t)(r * 128 + j * 16));
            uint32_t h01, h23, l01, l23;
            split4(v, h01, h23, l01, l23);
            *reinterpret_cast<uint2*>(sm + SM_ABF_HI + r * 80 + j * 8) = make_uint2(h01, h23);
            *reinterpret_cast<uint2*>(sm + SM_ABF_LO + r * 80 + j * 8) = make_uint2(l01, l23);
        }
        __syncthreads();

        issue_tile(c + 2);

        const uint32_t wbh = sb + STG_W_HI;
#pragma unroll
        for (int ks = 0; ks < 2; ks++) {
            const uint32_t akb = base + SM_ABF_HI + aoff + (uint32_t)(ks * 32);
            uint32_t ah[4][4], al[4][4], bb[4][2];
#pragma unroll
            for (int mf = 0; mf < 4; mf++) ldsm_x4(ah[mf], akb + (uint32_t)(mf * 1280));
#pragma unroll
            for (int p = 0; p < 2; p++) {
                uint32_t r4[4];
                uint32_t addr = wbh + (uint32_t)((wn * 32 + p * 16 + brow_off) * 80)
                                    + bk_off + (uint32_t)(ks * 32);
                ldsm_x4(r4, addr);
                bb[2*p][0] = r4[0]; bb[2*p][1] = r4[1];
                bb[2*p+1][0] = r4[2]; bb[2*p+1][1] = r4[3];
            }
#pragma unroll
            for (int mf = 0; mf < 4; mf++)
#pragma unroll
                for (int nf = 0; nf < 4; nf++) mma16816(acc[mf][nf], ah[mf], bb[nf]);
#pragma unroll
            for (int mf = 0; mf < 4; mf++) ldsm_x4(al[mf], akb + 20480u + (uint32_t)(mf * 1280));
#pragma unroll
            for (int mf = 0; mf < 4; mf++)
#pragma unroll
                for (int nf = 0; nf < 4; nf++) mma16816(acc[mf][nf], al[mf], bb[nf]);
#pragma unroll
            for (int p = 0; p < 2; p++) {
                uint32_t r4[4];
                uint32_t addr = wbh + 10240u + (uint32_t)((wn * 32 + p * 16 + brow_off) * 80)
                                    + bk_off + (uint32_t)(ks * 32);
                ldsm_x4(r4, addr);
                bb[2*p][0] = r4[0]; bb[2*p][1] = r4[1];
                bb[2*p+1][0] = r4[2]; bb[2*p+1][1] = r4[3];
            }
#pragma unroll
            for (int mf = 0; mf < 4; mf++)
#pragma unroll
                for (int nf = 0; nf < 4; nf++) mma16816(acc[mf][nf], ah[mf], bb[nf]);
        }
    }

    {
        const int gq = lid >> 2;
        const int t4 = lid & 3;
#pragma unroll
        for (int mf = 0; mf < 4; mf++) {
            const int row0 = m0 + wm * 64 + mf * 16 + gq;
#pragma unroll
            for (int nf = 0; nf < 4; nf++) {
                const int col = wn * 32 + nf * 8 + 2 * t4;
                const float b0 = s_bias[col], b1 = s_bias[col + 1];
                float* p0 = g_scores + (size_t)row0 * REDn + col;
                float* p1 = g_scores + (size_t)(row0 + 8) * REDn + col;
                *reinterpret_cast<float2*>(p0) =
                    make_float2(acc[mf][nf][0] + b0, acc[mf][nf][1] + b1);
                *reinterpret_cast<float2*>(p1) =
                    make_float2(acc[mf][nf][2] + b0, acc[mf][nf][3] + b1);
            }
        }
    }
}

// ============================================================
// Kernel 2: xg[M,192] = scores @ [wih_f;wih_b]^T + bias (fp32 f32x2)
// with per-CTA early exit on vlen.
// ============================================================
__global__ void __launch_bounds__(256) k_gemm2(
    const float* __restrict__ wih_f, const float* __restrict__ wih_b,
    const float* __restrict__ bih_f, const float* __restrict__ bih_b,
    const int* __restrict__ inputLength)
{
    const int m0 = blockIdx.x * 128;
    {
        const int vlen = inputLength[m0 >> 9] - 9;
        if ((m0 & 511) >= vlen) return;
    }

    __shared__ float As[16][128];
    __shared__ float Bs[16][64];
    const int tid = threadIdx.x;
    const int n0  = blockIdx.y * 64;
    const int txn = tid & 15;
    const int tym = tid >> 4;

    unsigned long long acc[8][2];
#pragma unroll
    for (int i = 0; i < 8; i++) { acc[i][0] = 0ull; acc[i][1] = 0ull; }

    for (int kt = 0; kt < REDn; kt += 16) {
#pragma unroll
        for (int ld = 0; ld < 2; ld++) {
            int lin = tid + ld * 256;
            int row = lin >> 2;
            int k4  = lin & 3;
            float4 v = *reinterpret_cast<const float4*>(&g_scores[(size_t)(m0 + row) * REDn + kt + k4 * 4]);
            As[k4 * 4 + 0][row] = v.x;
            As[k4 * 4 + 1][row] = v.y;
            As[k4 * 4 + 2][row] = v.z;
            As[k4 * 4 + 3][row] = v.w;
        }
        {
            int n  = tid >> 2;
            int k4 = tid & 3;
            int ng = n0 + n;
            const float* src = (ng < 96) ? (wih_f + (size_t)ng * REDn)
                                         : (wih_b + (size_t)(ng - 96) * REDn);
            float4 v = *reinterpret_cast<const float4*>(src + kt + k4 * 4);
            Bs[k4 * 4 + 0][n] = v.x;
            Bs[k4 * 4 + 1][n] = v.y;
            Bs[k4 * 4 + 2][n] = v.z;
            Bs[k4 * 4 + 3][n] = v.w;
        }
        __syncthreads();
#pragma unroll
        for (int kk = 0; kk < 16; kk++) {
            float4 a0 = *reinterpret_cast<const float4*>(&As[kk][tym * 8]);
            float4 a1 = *reinterpret_cast<const float4*>(&As[kk][tym * 8 + 4]);
            unsigned long long b0 = *reinterpret_cast<const unsigned long long*>(&Bs[kk][txn * 4]);
            unsigned long long b1 = *reinterpret_cast<const unsigned long long*>(&Bs[kk][txn * 4 + 2]);
            float avv[8] = {a0.x, a0.y, a0.z, a0.w, a1.x, a1.y, a1.z, a1.w};
#pragma unroll
            for (int i = 0; i < 8; i++) {
                unsigned long long ap = pack2(avv[i], avv[i]);
                acc[i][0] = ffma2(ap, b0, acc[i][0]);
                acc[i][1] = ffma2(ap, b1, acc[i][1]);
            }
        }
        __syncthreads();
    }
    const int nb = n0 + txn * 4;
    float bv[4];
#pragma unroll
    for (int jj = 0; jj < 4; jj++) {
        int ngj = nb + jj;
        bv[jj] = (ngj < 96) ? bih_f[ngj] : bih_b[ngj - 96];
    }
#pragma unroll
    for (int i = 0; i < 8; i++) {
        int mg = m0 + tym * 8 + i;
        float2 f0 = unpack2(acc[i][0]);
        float2 f1 = unpack2(acc[i][1]);
        *reinterpret_cast<float4*>(&g_xg[(size_t)mg * 192 + nb]) =
            make_float4(f0.x + bv[0], f0.y + bv[1], f1.x + bv[2], f1.y + bv[3]);
    }
}

// ============================================================
// Kernel 3: masked GRU — one warp per (batch, direction), loop to vlen.
// TRUE prefetch depth 6 (register ring, unroll x6); rcp.approx activations.
// ============================================================
__global__ void __launch_bounds__(32) k_gru(
    const int*   __restrict__ inputLength,
    const float* __restrict__ whh_f, const float* __restrict__ whh_b,
    const float* __restrict__ bhh_f, const float* __restrict__ bhh_b)
{
    const int b   = blockIdx.x;
    const int dir = blockIdx.y;
    const int j   = threadIdx.x;   // 0..31

    const float* whh = dir ? whh_b : whh_f;
    const float* bhh = dir ? bhh_b : bhh_f;

    unsigned long long wr[16], wz[16], wn2[16];
    const float2* wrp = reinterpret_cast<const float2*>(whh + j * 32);
    const float2* wzp = reinterpret_cast<const float2*>(whh + (32 + j) * 32);
    const float2* wnp = reinterpret_cast<const float2*>(whh + (64 + j) * 32);
#pragma unroll
    for (int i = 0; i < 16; i++) {
        float2 a = wrp[i], cz = wzp[i], d = wnp[i];
        wr[i]  = pack2(a.x, a.y);
        wz[i]  = pack2(cz.x, cz.y);
        wn2[i] = pack2(d.x, d.y);
    }
    const float br = bhh[j], bz = bhh[32 + j], bn = bhh[64 + j];

    __shared__ __align__(16) float sh[2][32];

    const int vlen = inputLength[b] - 9;   // >= 191
    float* outp = (dir ? g_outB : g_outF) + (size_t)b * Tn * Hn + j;
    const float* xgbase = g_xg + (size_t)b * Tn * 192 + dir * 96;

    // register ring: 6 sets (vlen >= 191 >> 6, all preloads valid)
    float xr0,xz0,xn0, xr1,xz1,xn1, xr2,xz2,xn2, xr3,xz3,xn3, xr4,xz4,xn4, xr5,xz5,xn5;
#define PRELOAD(K, XR, XZ, XN)                                                \
    {                                                                         \
        const float* x = xgbase + (size_t)(dir ? (vlen - 1 - (K)) : (K)) * 192; \
        XR = x[j]; XZ = x[32 + j]; XN = x[64 + j];                            \
    }
    PRELOAD(0, xr0, xz0, xn0)
    PRELOAD(1, xr1, xz1, xn1)
    PRELOAD(2, xr2, xz2, xn2)
    PRELOAD(3, xr3, xz3, xn3)
    PRELOAD(4, xr4, xz4, xn4)
    PRELOAD(5, xr5, xz5, xn5)
#undef PRELOAD

    float h = 0.f;
    int s = 0;

#define GRU_STEP(XR, XZ, XN)                                                  \
    {                                                                         \
        const float cxr = XR, cxz = XZ, cxn = XN;                             \
        const int sp = s + 6;                                                 \
        if (sp < vlen) {                                                      \
            const float* x = xgbase + (size_t)(dir ? (vlen - 1 - sp) : sp) * 192; \
            XR = x[j]; XZ = x[32 + j]; XN = x[64 + j];                        \
        }                                                                     \
        sh[s & 1][j] = h;                                                     \
        __syncwarp();                                                         \
        const unsigned long long* hp =                                        \
            reinterpret_cast<const unsigned long long*>(&sh[s & 1][0]);       \
        unsigned long long ar0 = 0ull, ar1 = 0ull;                            \
        unsigned long long az0 = 0ull, az1 = 0ull;                            \
        unsigned long long an0 = 0ull, an1 = 0ull;                            \
        _Pragma("unroll")                                                     \
        for (int i = 0; i < 16; i += 2) {                                     \
            unsigned long long hv0 = hp[i];                                   \
            unsigned long long hv1 = hp[i + 1];                               \
            ar0 = ffma2(hv0, wr[i],      ar0);                                \
            ar1 = ffma2(hv1, wr[i + 1],  ar1);                                \
            az0 = ffma2(hv0, wz[i],      az0);                                \
            az1 = ffma2(hv1, wz[i + 1],  az1);                                \
            an0 = ffma2(hv0, wn2[i],     an0);                                \
            an1 = ffma2(hv1, wn2[i + 1], an1);                                \
        }                                                                     \
        float2 fr = unpack2(fadd2(ar0, ar1));                                 \
        float2 fz = unpack2(fadd2(az0, az1));                                 \
        float2 fn = unpack2(fadd2(an0, an1));                                 \
        float hgr = fr.x + fr.y + br;                                         \
        float hgz = fz.x + fz.y + bz;                                         \
        float hgn = fn.x + fn.y + bn;                                         \
        float r  = sigmoid_fast(cxr + hgr);                                   \
        float z  = sigmoid_fast(cxz + hgz);                                   \
        float nn = tanh_fast(__fmaf_rn(r, hgn, cxn));                         \
        h = __fmaf_rn(z, h - nn, nn);                                         \
        int tout = dir ? (vlen - 1 - s) : s;                                  \
        outp[(size_t)tout * Hn] = h;                                          \
        s++;                                                                  \
    }

    while (s + 6 <= vlen) {
        GRU_STEP(xr0, xz0, xn0)
        GRU_STEP(xr1, xz1, xn1)
        GRU_STEP(xr2, xz2, xn2)
        GRU_STEP(xr3, xz3, xn3)
        GRU_STEP(xr4, xz4, xn4)
        GRU_STEP(xr5, xz5, xn5)
    }
    if (s < vlen) GRU_STEP(xr0, xz0, xn0)
    if (s < vlen) GRU_STEP(xr1, xz1, xn1)
    if (s < vlen) GRU_STEP(xr2, xz2, xn2)
    if (s < vlen) GRU_STEP(xr3, xz3, xn3)
    if (s < vlen) GRU_STEP(xr4, xz4, xn4)
#undef GRU_STEP
}

// ============================================================
// Kernel 4: q projection + MLP + argmax-selected TP score.
// ============================================================
__global__ void __launch_bounds__(512) k_final(
    const int*   __restrict__ inputLength,
    const float* __restrict__ qw,  const float* __restrict__ qb,
    const float* __restrict__ m1w, const float* __restrict__ m1b,
    const float* __restrict__ m2w, const float* __restrict__ m2b,
    float* __restrict__ out)
{
    const int b = blockIdx.x;
    const int t = threadIdx.x;
    __shared__ float sq[512];
    __shared__ float sh1[32];
    __shared__ int   s_tau;
    __shared__ float wsum[16];

    const int vlen = inputLength[b] - 9;

    float qv = 0.f;
    if (t < vlen) {
        const float* of = g_outF + ((size_t)b * Tn + t) * Hn;
        const float* ob = g_outB + ((size_t)b * Tn + t) * Hn;
        float a = qb[0];
#pragma unroll
        for (int jj = 0; jj < 32; jj++) a += of[jj] * qw[jj] + ob[jj] * qw[32 + jj];
        qv = a;
    }
    sq[t] = qv;
    __syncthreads();

    if (t < 32) {
        const float* lf = g_outF + ((size_t)b * Tn + (vlen - 1)) * Hn;
        const float* lb = g_outB + ((size_t)b * Tn) * Hn;
        float a = m1b[t];
#pragma unroll
        for (int jj = 0; jj < 32; jj++) a += lf[jj] * m1w[t * 64 + jj] + lb[jj] * m1w[t * 64 + 32 + jj];
        sh1[t] = fmaxf(a, 0.f);
    }
    __syncthreads();
    if (t == 0) {
        float best = -3.0e38f; int bi = 0;
#pragma unroll
        for (int c = 0; c < 5; c++) {
            float v = m2b[c];
#pragma unroll
            for (int o = 0; o < 32; o++) v += sh1[o] * m2w[c * 32 + o];
            if (v > best) { best = v; bi = c; }
        }
        s_tau = 8 + 2 * bi;
    }
    __syncthreads();

    const int tau = s_tau;
    float pm = 0.f;
    if (t < vlen) {
        float l = 3.0e38f;
        for (int k = 0; k < tau; k++) {
            int idx = t - k;
            float v = (idx >= 0) ? sq[idx] : 3.0e38f;
            l = fminf(l, v);
        }
        float msum = 0.f, nsum = 0.f;
        for (int k = 0; k < tau; k++) {
            int idx = t + k;
            if (idx < vlen) {
                float w = __expf(-sq[idx]);
                nsum += w;
                msum += sq[idx] * w;
            }
        }
        float ratio = (nsum > 0.f) ? (msum / nsum) : 0.f;
        pm = 0.5f * (ratio + l);
    }
    float v = pm;
#pragma unroll
    for (int o = 16; o > 0; o >>= 1) v += __shfl_down_sync(0xffffffffu, v, o);
    if ((t & 31) == 0) wsum[t >> 5] = v;
    __syncthreads();
    if (t == 0) {
        float s = 0.f;
#pragma unroll
        for (int w = 0; w < 16; w++) s += wsum[w];
        out[b] = s / (float)vlen;
    }
}

// ============================================================
extern "C" void kernel_launch(void* const* d_in, const int* in_sizes, int n_in,
                              void* d_out, int out_size) {
    (void)in_sizes; (void)n_in; (void)out_size;
    const float* motion   = (const float*)d_in[0];
    const float* content  = (const float*)d_in[1];
    const float* distort  = (const float*)d_in[2];
    const int*   inlen    = (const int*)  d_in[3];
    const float* fc0w     = (const float*)d_in[4];
    const float* fc0b     = (const float*)d_in[5];
    const float* wih_f    = (const float*)d_in[6];
    const float* whh_f    = (const float*)d_in[7];
    const float* bih_f    = (const float*)d_in[8];
    const float* bhh_f    = (const float*)d_in[9];
    const float* wih_b    = (const float*)d_in[10];
    const float* whh_b    = (const float*)d_in[11];
    const float* bih_b    = (const float*)d_in[12];
    const float* bhh_b    = (const float*)d_in[13];
    const float* qw       = (const float*)d_in[14];
    const float* qb       = (const float*)d_in[15];
    const float* m1w      = (const float*)d_in[16];
    const float* m1b      = (const float*)d_in[17];
    const float* m2w      = (const float*)d_in[18];
    const float* m2b      = (const float*)d_in[19];
    float* out = (float*)d_out;

    cudaFuncSetAttribute(k_gemm1_mma, cudaFuncAttributeMaxDynamicSharedMemorySize, DYN_SMEM);

    k_prep_w<<<(REDn * DT + 255) / 256, 256>>>(fc0w);
    k_gemm1_mma<<<Mrows / MT, 512, DYN_SMEM>>>(content, distort, motion, fc0b, inlen);
    k_gemm2<<<dim3(Mrows / 128, 3), 256>>>(wih_f, wih_b, bih_f, bih_b, inlen);
    k_gru<<<dim3(Bn, 2), 32>>>(inlen, whh_f, whh_b, bhh_f, bhh_b);
    k_final<<<Bn, 512>>>(inlen, qw, qb, m1w, m1b, m2w, m2b, out);
}

// round 12
// speedup vs baseline: 1.0740x; 1.0042x over previous
#include <cuda_runtime.h>
#include <cuda_bf16.h>
#include <cstdint>

#define Bn   64
#define Tn   512
#define Hn   32
#define REDn 128
#define DC   4096
#define DD   512
#define DM   256
#define DT   4864
#define Mrows (Bn*Tn)   // 32768

#define KT    32              // bf16 K per tile
#define NKT   (DT/KT)         // 152 k-tiles
#define MT    256             // M rows per CTA

// -------- scratch (static __device__, no allocations) --------
__device__ float g_scores[(size_t)Mrows * REDn];          // 16 MB
__device__ float g_xg[(size_t)Mrows * 192];               // 24 MB
__device__ float g_outF[(size_t)Mrows * Hn];              // 4 MB
__device__ float g_outB[(size_t)Mrows * Hn];              // 4 MB
__device__ __nv_bfloat16 g_Whi[(size_t)REDn * DT];        // 1.25 MB
__device__ __nv_bfloat16 g_Wlo[(size_t)REDn * DT];        // 1.25 MB

// ============================================================
// helpers
// ============================================================
__device__ __forceinline__ uint32_t smem_u32(const void* p) {
    uint32_t a;
    asm("{ .reg .u64 t; cvta.to.shared.u64 t, %1; cvt.u32.u64 %0, t; }" : "=r"(a) : "l"(p));
    return a;
}
__device__ __forceinline__ void cp16(uint32_t dst, const void* src) {
    asm volatile("cp.async.cg.shared.global [%0], [%1], 16;" :: "r"(dst), "l"(src) : "memory");
}
__device__ __forceinline__ void cp_commit() {
    asm volatile("cp.async.commit_group;" ::: "memory");
}
__device__ __forceinline__ void cp_wait3() {
    asm volatile("cp.async.wait_group 3;" ::: "memory");
}
__device__ __forceinline__ void ldsm_x4(uint32_t* r, uint32_t addr) {
    asm volatile("ldmatrix.sync.aligned.m8n8.x4.shared.b16 {%0,%1,%2,%3}, [%4];"
                 : "=r"(r[0]), "=r"(r[1]), "=r"(r[2]), "=r"(r[3]) : "r"(addr));
}
__device__ __forceinline__ void mma16816(float* c, const uint32_t* a, const uint32_t* b) {
    asm volatile("mma.sync.aligned.m16n8k16.row.col.f32.bf16.bf16.f32 "
                 "{%0,%1,%2,%3}, {%4,%5,%6,%7}, {%8,%9}, {%0,%1,%2,%3};"
                 : "+f"(c[0]), "+f"(c[1]), "+f"(c[2]), "+f"(c[3])
                 : "r"(a[0]), "r"(a[1]), "r"(a[2]), "r"(a[3]), "r"(b[0]), "r"(b[1]));
}
__device__ __forceinline__ void split4(float4 v, uint32_t& h01, uint32_t& h23,
                                       uint32_t& l01, uint32_t& l23) {
    __nv_bfloat16 h0 = __float2bfloat16_rn(v.x);
    __nv_bfloat16 h1 = __float2bfloat16_rn(v.y);
    __nv_bfloat16 h2 = __float2bfloat16_rn(v.z);
    __nv_bfloat16 h3 = __float2bfloat16_rn(v.w);
    float r0 = v.x - __bfloat162float(h0);
    float r1 = v.y - __bfloat162float(h1);
    float r2 = v.z - __bfloat162float(h2);
    float r3 = v.w - __bfloat162float(h3);
    __nv_bfloat162 H0 = __halves2bfloat162(h0, h1);
    __nv_bfloat162 H1 = __halves2bfloat162(h2, h3);
    __nv_bfloat162 L0 = __floats2bfloat162_rn(r0, r1);
    __nv_bfloat162 L1 = __floats2bfloat162_rn(r2, r3);
    h01 = *reinterpret_cast<uint32_t*>(&H0);
    h23 = *reinterpret_cast<uint32_t*>(&H1);
    l01 = *reinterpret_cast<uint32_t*>(&L0);
    l23 = *reinterpret_cast<uint32_t*>(&L1);
}
// packed dual-fp32 ops
__device__ __forceinline__ unsigned long long pack2(float x, float y) {
    unsigned long long r;
    asm("mov.b64 %0, {%1,%2};" : "=l"(r) : "f"(x), "f"(y));
    return r;
}
__device__ __forceinline__ unsigned long long ffma2(unsigned long long a,
                                                    unsigned long long b,
                                                    unsigned long long c) {
    unsigned long long d;
    asm("fma.rn.f32x2 %0, %1, %2, %3;" : "=l"(d) : "l"(a), "l"(b), "l"(c));
    return d;
}
__device__ __forceinline__ unsigned long long fadd2(unsigned long long a,
                                                    unsigned long long b) {
    unsigned long long d;
    asm("add.rn.f32x2 %0, %1, %2;" : "=l"(d) : "l"(a), "l"(b));
    return d;
}
__device__ __forceinline__ float2 unpack2(unsigned long long v) {
    float2 f;
    asm("mov.b64 {%0,%1}, %2;" : "=f"(f.x), "=f"(f.y) : "l"(v));
    return f;
}
__device__ __forceinline__ float rcp_fast(float x) {
    float y;
    asm("rcp.approx.f32 %0, %1;" : "=f"(y) : "f"(x));
    return y;
}
__device__ __forceinline__ float sigmoid_fast(float x) {
    return rcp_fast(1.f + __expf(-x));
}
__device__ __forceinline__ float tanh_fast(float x) {
    return __fmaf_rn(2.f, rcp_fast(1.f + __expf(-2.f * x)), -1.f);
}

// ============================================================
// Kernel 0: split fc0_w into bf16 hi/lo
// ============================================================
__global__ void __launch_bounds__(256) k_prep_w(const float* __restrict__ W) {
    int i = blockIdx.x * 256 + threadIdx.x;
    if (i < REDn * DT) {
        float x = W[i];
        __nv_bfloat16 h = __float2bfloat16_rn(x);
        g_Whi[i] = h;
        g_Wlo[i] = __float2bfloat16_rn(x - __bfloat162float(h));
    }
}

// ============================================================
// Kernel 1: mma.sync split-bf16 GEMM, MT=256, 16 warps (4m x 4n),
// warp tile 64x32. NO fp32 staging: A loaded to REGISTERS (LDG.128),
// split to bf16 in regs, STS direct to A_hi/A_lo. W in its own
// 4-stage cp.async ring (wait_group 3). Early exit per tile.
//
// SMEM (1024-aligned base):
//   [0     :20480)  A_hi bf16 [256 x 80B pad]
//   [20480 :40960)  A_lo
//   W ring stage s at 40960 + s*20480: W_hi 10240 | W_lo 10240
// ============================================================
#define SM_ABF_HI 0u
#define SM_ABF_LO 20480u
#define SM_WRING  40960u
#define WSTG      20480u
#define DYN_SMEM  (40960 + 4*20480 + 1024)   // 123904

__global__ void __launch_bounds__(512, 1) k_gemm1_mma(
    const float* __restrict__ content, const float* __restrict__ distort,
    const float* __restrict__ motion,  const float* __restrict__ bias,
    const int* __restrict__ inputLength)
{
    const int m0 = blockIdx.x * MT;
    {   // early exit: tile rows all >= vlen of this batch
        const int vlen = inputLength[m0 >> 9] - 9;
        if ((m0 & 511) >= vlen) return;
    }

    extern __shared__ char dynsmem[];
    __shared__ float s_bias[128];

    const int tid = threadIdx.x;
    const int wid = tid >> 5;
    const int lid = tid & 31;
    const int wm  = wid & 3;     // 4 m-warps x 64 rows
    const int wn  = wid >> 2;    // 4 n-warps x 32 cols

    const uint32_t raw  = smem_u32(dynsmem);
    const uint32_t base = (raw + 1023u) & ~1023u;
    char* sm = dynsmem + (base - raw);

    if (tid < 128) s_bias[tid] = bias[tid];

    const int hrow = tid >> 2;   // W row 0..127
    const int jw   = tid & 3;

    // A chunk constants: 4 chunks/thread; chunk = i*512+tid -> r = chunk>>3, j = chunk&7
    const int ar0 = tid >> 3;    // row for i=0 (rows step +64 per i)
    const int aj  = tid & 7;

    const uint32_t aoff = (uint32_t)((wm * 64 + (lid & 15)) * 80 + ((lid >> 4) << 4));
    const int g3 = lid >> 3;
    const uint32_t brow_off = (uint32_t)(((g3 >> 1) << 3) + (lid & 7));
    const uint32_t bk_off   = (uint32_t)((g3 & 1) * 16);

    float acc[4][4][4];
#pragma unroll
    for (int i = 0; i < 4; i++)
#pragma unroll
        for (int j = 0; j < 4; j++)
#pragma unroll
            for (int k = 0; k < 4; k++) acc[i][j][k] = 0.f;

    float4 areg[4];

    auto load_a = [&](int c) {
        if (c < NKT) {
            const int kt = c * KT;
            const float* asrc; int astr, koff;
            if (kt < DC)           { asrc = content; astr = DC; koff = kt; }
            else if (kt < DC + DD) { asrc = distort; astr = DD; koff = kt - DC; }
            else                   { asrc = motion;  astr = DM; koff = kt - DC - DD; }
#pragma unroll
            for (int i = 0; i < 4; ++i) {
                int r = ar0 + i * 64;
                areg[i] = *reinterpret_cast<const float4*>(
                    asrc + (size_t)(m0 + r) * astr + koff + aj * 4);
            }
        }
    };

    auto issue_w = [&](int c) {
        if (c < NKT) {
            const int kt = c * KT;
            const uint32_t wb = base + SM_WRING + (uint32_t)(c & 3) * WSTG;
            cp16(wb + (uint32_t)(hrow * 80 + jw * 16),
                 (const char*)g_Whi + ((size_t)hrow * DT + kt) * 2 + jw * 16);
            cp16(wb + 10240u + (uint32_t)(hrow * 80 + jw * 16),
                 (const char*)g_Wlo + ((size_t)hrow * DT + kt) * 2 + jw * 16);
        }
        cp_commit();
    };

    // prologue
    load_a(0);
    issue_w(0);
    issue_w(1);
    issue_w(2);

    for (int c = 0; c < NKT; ++c) {
        __syncthreads();   // all warps done reading A_bf(c-1) and W stage (c+3)&3

        // split A(c) from registers -> A_hi / A_lo (padded rows)
#pragma unroll
        for (int i = 0; i < 4; ++i) {
            int r = ar0 + i * 64;
            uint32_t h01, h23, l01, l23;
            split4(areg[i], h01, h23, l01, l23);
            *reinterpret_cast<uint2*>(sm + SM_ABF_HI + r * 80 + aj * 8) = make_uint2(h01, h23);
            *reinterpret_cast<uint2*>(sm + SM_ABF_LO + r * 80 + aj * 8) = make_uint2(l01, l23);
        }
        load_a(c + 1);     // LDG for next tile (consumed next iteration)
        issue_w(c + 3);    // W ring stays 3 stages ahead
        cp_wait3();        // W(c) resident
        __syncthreads();   // A_bf(c) visible

        const uint32_t wbh = base + SM_WRING + (uint32_t)(c & 3) * WSTG;
#pragma unroll
        for (int ks = 0; ks < 2; ks++) {
            const uint32_t akb = base + SM_ABF_HI + aoff + (uint32_t)(ks * 32);
            uint32_t ah[4][4], al[4][4], bb[4][2];
#pragma unroll
            for (int mf = 0; mf < 4; mf++) ldsm_x4(ah[mf], akb + (uint32_t)(mf * 1280));
#pragma unroll
            for (int p = 0; p < 2; p++) {
                uint32_t r4[4];
                uint32_t addr = wbh + (uint32_t)((wn * 32 + p * 16 + brow_off) * 80)
                                    + bk_off + (uint32_t)(ks * 32);
                ldsm_x4(r4, addr);
                bb[2*p][0] = r4[0]; bb[2*p][1] = r4[1];
                bb[2*p+1][0] = r4[2]; bb[2*p+1][1] = r4[3];
            }
#pragma unroll
            for (int mf = 0; mf < 4; mf++)
#pragma unroll
                for (int nf = 0; nf < 4; nf++) mma16816(acc[mf][nf], ah[mf], bb[nf]);
#pragma unroll
            for (int mf = 0; mf < 4; mf++) ldsm_x4(al[mf], akb + 20480u + (uint32_t)(mf * 1280));
#pragma unroll
            for (int mf = 0; mf < 4; mf++)
#pragma unroll
                for (int nf = 0; nf < 4; nf++) mma16816(acc[mf][nf], al[mf], bb[nf]);
#pragma unroll
            for (int p = 0; p < 2; p++) {
                uint32_t r4[4];
                uint32_t addr = wbh + 10240u + (uint32_t)((wn * 32 + p * 16 + brow_off) * 80)
                                    + bk_off + (uint32_t)(ks * 32);
                ldsm_x4(r4, addr);
                bb[2*p][0] = r4[0]; bb[2*p][1] = r4[1];
                bb[2*p+1][0] = r4[2]; bb[2*p+1][1] = r4[3];
            }
#pragma unroll
            for (int mf = 0; mf < 4; mf++)
#pragma unroll
                for (int nf = 0; nf < 4; nf++) mma16816(acc[mf][nf], ah[mf], bb[nf]);
        }
    }

    {
        const int gq = lid >> 2;
        const int t4 = lid & 3;
#pragma unroll
        for (int mf = 0; mf < 4; mf++) {
            const int row0 = m0 + wm * 64 + mf * 16 + gq;
#pragma unroll
            for (int nf = 0; nf < 4; nf++) {
                const int col = wn * 32 + nf * 8 + 2 * t4;
                const float b0 = s_bias[col], b1 = s_bias[col + 1];
                float* p0 = g_scores + (size_t)row0 * REDn + col;
                float* p1 = g_scores + (size_t)(row0 + 8) * REDn + col;
                *reinterpret_cast<float2*>(p0) =
                    make_float2(acc[mf][nf][0] + b0, acc[mf][nf][1] + b1);
                *reinterpret_cast<float2*>(p1) =
                    make_float2(acc[mf][nf][2] + b0, acc[mf][nf][3] + b1);
            }
        }
    }
}

// ============================================================
// Kernel 2: xg[M,192] = scores @ [wih_f;wih_b]^T + bias (fp32 f32x2)
// with per-CTA early exit on vlen.
// ============================================================
__global__ void __launch_bounds__(256) k_gemm2(
    const float* __restrict__ wih_f, const float* __restrict__ wih_b,
    const float* __restrict__ bih_f, const float* __restrict__ bih_b,
    const int* __restrict__ inputLength)
{
    const int m0 = blockIdx.x * 128;
    {
        const int vlen = inputLength[m0 >> 9] - 9;
        if ((m0 & 511) >= vlen) return;
    }

    __shared__ float As[16][128];
    __shared__ float Bs[16][64];
    const int tid = threadIdx.x;
    const int n0  = blockIdx.y * 64;
    const int txn = tid & 15;
    const int tym = tid >> 4;

    unsigned long long acc[8][2];
#pragma unroll
    for (int i = 0; i < 8; i++) { acc[i][0] = 0ull; acc[i][1] = 0ull; }

    for (int kt = 0; kt < REDn; kt += 16) {
#pragma unroll
        for (int ld = 0; ld < 2; ld++) {
            int lin = tid + ld * 256;
            int row = lin >> 2;
            int k4  = lin & 3;
            float4 v = *reinterpret_cast<const float4*>(&g_scores[(size_t)(m0 + row) * REDn + kt + k4 * 4]);
            As[k4 * 4 + 0][row] = v.x;
            As[k4 * 4 + 1][row] = v.y;
            As[k4 * 4 + 2][row] = v.z;
            As[k4 * 4 + 3][row] = v.w;
        }
        {
            int n  = tid >> 2;
            int k4 = tid & 3;
            int ng = n0 + n;
            const float* src = (ng < 96) ? (wih_f + (size_t)ng * REDn)
                                         : (wih_b + (size_t)(ng - 96) * REDn);
            float4 v = *reinterpret_cast<const float4*>(src + kt + k4 * 4);
            Bs[k4 * 4 + 0][n] = v.x;
            Bs[k4 * 4 + 1][n] = v.y;
            Bs[k4 * 4 + 2][n] = v.z;
            Bs[k4 * 4 + 3][n] = v.w;
        }
        __syncthreads();
#pragma unroll
        for (int kk = 0; kk < 16; kk++) {
            float4 a0 = *reinterpret_cast<const float4*>(&As[kk][tym * 8]);
            float4 a1 = *reinterpret_cast<const float4*>(&As[kk][tym * 8 + 4]);
            unsigned long long b0 = *reinterpret_cast<const unsigned long long*>(&Bs[kk][txn * 4]);
            unsigned long long b1 = *reinterpret_cast<const unsigned long long*>(&Bs[kk][txn * 4 + 2]);
            float avv[8] = {a0.x, a0.y, a0.z, a0.w, a1.x, a1.y, a1.z, a1.w};
#pragma unroll
            for (int i = 0; i < 8; i++) {
                unsigned long long ap = pack2(avv[i], avv[i]);
                acc[i][0] = ffma2(ap, b0, acc[i][0]);
                acc[i][1] = ffma2(ap, b1, acc[i][1]);
            }
        }
        __syncthreads();
    }
    const int nb = n0 + txn * 4;
    float bv[4];
#pragma unroll
    for (int jj = 0; jj < 4; jj++) {
        int ngj = nb + jj;
        bv[jj] = (ngj < 96) ? bih_f[ngj] : bih_b[ngj - 96];
    }
#pragma unroll
    for (int i = 0; i < 8; i++) {
        int mg = m0 + tym * 8 + i;
        float2 f0 = unpack2(acc[i][0]);
        float2 f1 = unpack2(acc[i][1]);
        *reinterpret_cast<float4*>(&g_xg[(size_t)mg * 192 + nb]) =
            make_float4(f0.x + bv[0], f0.y + bv[1], f1.x + bv[2], f1.y + bv[3]);
    }
}

// ============================================================
// Kernel 3: masked GRU — one warp per (batch, direction), loop to vlen.
// TRUE prefetch depth 6 (register ring, unroll x6); rcp.approx activations.
// ============================================================
__global__ void __launch_bounds__(32) k_gru(
    const int*   __restrict__ inputLength,
    const float* __restrict__ whh_f, const float* __restrict__ whh_b,
    const float* __restrict__ bhh_f, const float* __restrict__ bhh_b)
{
    const int b   = blockIdx.x;
    const int dir = blockIdx.y;
    const int j   = threadIdx.x;   // 0..31

    const float* whh = dir ? whh_b : whh_f;
    const float* bhh = dir ? bhh_b : bhh_f;

    unsigned long long wr[16], wz[16], wn2[16];
    const float2* wrp = reinterpret_cast<const float2*>(whh + j * 32);
    const float2* wzp = reinterpret_cast<const float2*>(whh + (32 + j) * 32);
    const float2* wnp = reinterpret_cast<const float2*>(whh + (64 + j) * 32);
#pragma unroll
    for (int i = 0; i < 16; i++) {
        float2 a = wrp[i], cz = wzp[i], d = wnp[i];
        wr[i]  = pack2(a.x, a.y);
        wz[i]  = pack2(cz.x, cz.y);
        wn2[i] = pack2(d.x, d.y);
    }
    const float br = bhh[j], bz = bhh[32 + j], bn = bhh[64 + j];

    __shared__ __align__(16) float sh[2][32];

    const int vlen = inputLength[b] - 9;   // >= 191
    float* outp = (dir ? g_outB : g_outF) + (size_t)b * Tn * Hn + j;
    const float* xgbase = g_xg + (size_t)b * Tn * 192 + dir * 96;

    // register ring: 6 sets (vlen >= 191 >> 6, all preloads valid)
    float xr0,xz0,xn0, xr1,xz1,xn1, xr2,xz2,xn2, xr3,xz3,xn3, xr4,xz4,xn4, xr5,xz5,xn5;
#define PRELOAD(K, XR, XZ, XN)                                                \
    {                                                                         \
        const float* x = xgbase + (size_t)(dir ? (vlen - 1 - (K)) : (K)) * 192; \
        XR = x[j]; XZ = x[32 + j]; XN = x[64 + j];                            \
    }
    PRELOAD(0, xr0, xz0, xn0)
    PRELOAD(1, xr1, xz1, xn1)
    PRELOAD(2, xr2, xz2, xn2)
    PRELOAD(3, xr3, xz3, xn3)
    PRELOAD(4, xr4, xz4, xn4)
    PRELOAD(5, xr5, xz5, xn5)
#undef PRELOAD

    float h = 0.f;
    int s = 0;

#define GRU_STEP(XR, XZ, XN)                                                  \
    {                                                                         \
        const float cxr = XR, cxz = XZ, cxn = XN;                             \
        const int sp = s + 6;                                                 \
        if (sp < vlen) {                                                      \
            const float* x = xgbase + (size_t)(dir ? (vlen - 1 - sp) : sp) * 192; \
            XR = x[j]; XZ = x[32 + j]; XN = x[64 + j];                        \
        }                                                                     \
        sh[s & 1][j] = h;                                                     \
        __syncwarp();                                                         \
        const unsigned long long* hp =                                        \
            reinterpret_cast<const unsigned long long*>(&sh[s & 1][0]);       \
        unsigned long long ar0 = 0ull, ar1 = 0ull;                            \
        unsigned long long az0 = 0ull, az1 = 0ull;                            \
        unsigned long long an0 = 0ull, an1 = 0ull;                            \
        _Pragma("unroll")                                                     \
        for (int i = 0; i < 16; i += 2) {                                     \
            unsigned long long hv0 = hp[i];                                   \
            unsigned long long hv1 = hp[i + 1];                               \
            ar0 = ffma2(hv0, wr[i],      ar0);                                \
            ar1 = ffma2(hv1, wr[i + 1],  ar1);                                \
            az0 = ffma2(hv0, wz[i],      az0);                                \
            az1 = ffma2(hv1, wz[i + 1],  az1);                                \
            an0 = ffma2(hv0, wn2[i],     an0);                                \
            an1 = ffma2(hv1, wn2[i + 1], an1);                                \
        }                                                                     \
        float2 fr = unpack2(fadd2(ar0, ar1));                                 \
        float2 fz = unpack2(fadd2(az0, az1));                                 \
        float2 fn = unpack2(fadd2(an0, an1));                                 \
        float hgr = fr.x + fr.y + br;                                         \
        float hgz = fz.x + fz.y + bz;                                         \
        float hgn = fn.x + fn.y + bn;                                         \
        float r  = sigmoid_fast(cxr + hgr);                                   \
        float z  = sigmoid_fast(cxz + hgz);                                   \
        float nn = tanh_fast(__fmaf_rn(r, hgn, cxn));                         \
        h = __fmaf_rn(z, h - nn, nn);                                         \
        int tout = dir ? (vlen - 1 - s) : s;                                  \
        outp[(size_t)tout * Hn] = h;                                          \
        s++;                                                                  \
    }

    while (s + 6 <= vlen) {
        GRU_STEP(xr0, xz0, xn0)
        GRU_STEP(xr1, xz1, xn1)
        GRU_STEP(xr2, xz2, xn2)
        GRU_STEP(xr3, xz3, xn3)
        GRU_STEP(xr4, xz4, xn4)
        GRU_STEP(xr5, xz5, xn5)
    }
    if (s < vlen) GRU_STEP(xr0, xz0, xn0)
    if (s < vlen) GRU_STEP(xr1, xz1, xn1)
    if (s < vlen) GRU_STEP(xr2, xz2, xn2)
    if (s < vlen) GRU_STEP(xr3, xz3, xn3)
    if (s < vlen) GRU_STEP(xr4, xz4, xn4)
#undef GRU_STEP
}

// ============================================================
// Kernel 4: q projection + MLP + argmax-selected TP score.
// ============================================================
__global__ void __launch_bounds__(512) k_final(
    const int*   __restrict__ inputLength,
    const float* __restrict__ qw,  const float* __restrict__ qb,
    const float* __restrict__ m1w, const float* __restrict__ m1b,
    const float* __restrict__ m2w, const float* __restrict__ m2b,
    float* __restrict__ out)
{
    const int b = blockIdx.x;
    const int t = threadIdx.x;
    __shared__ float sq[512];
    __shared__ float sh1[32];
    __shared__ int   s_tau;
    __shared__ float wsum[16];

    const int vlen = inputLength[b] - 9;

    float qv = 0.f;
    if (t < vlen) {
        const float* of = g_outF + ((size_t)b * Tn + t) * Hn;
        const float* ob = g_outB + ((size_t)b * Tn + t) * Hn;
        float a = qb[0];
#pragma unroll
        for (int jj = 0; jj < 32; jj++) a += of[jj] * qw[jj] + ob[jj] * qw[32 + jj];
        qv = a;
    }
    sq[t] = qv;
    __syncthreads();

    if (t < 32) {
        const float* lf = g_outF + ((size_t)b * Tn + (vlen - 1)) * Hn;
        const float* lb = g_outB + ((size_t)b * Tn) * Hn;
        float a = m1b[t];
#pragma unroll
        for (int jj = 0; jj < 32; jj++) a += lf[jj] * m1w[t * 64 + jj] + lb[jj] * m1w[t * 64 + 32 + jj];
        sh1[t] = fmaxf(a, 0.f);
    }
    __syncthreads();
    if (t == 0) {
        float best = -3.0e38f; int bi = 0;
#pragma unroll
        for (int c = 0; c < 5; c++) {
            float v = m2b[c];
#pragma unroll
            for (int o = 0; o < 32; o++) v += sh1[o] * m2w[c * 32 + o];
            if (v > best) { best = v; bi = c; }
        }
        s_tau = 8 + 2 * bi;
    }
    __syncthreads();

    const int tau = s_tau;
    float pm = 0.f;
    if (t < vlen) {
        float l = 3.0e38f;
        for (int k = 0; k < tau; k++) {
            int idx = t - k;
            float v = (idx >= 0) ? sq[idx] : 3.0e38f;
            l = fminf(l, v);
        }
        float msum = 0.f, nsum = 0.f;
        for (int k = 0; k < tau; k++) {
            int idx = t + k;
            if (idx < vlen) {
                float w = __expf(-sq[idx]);
                nsum += w;
                msum += sq[idx] * w;
            }
        }
        float ratio = (nsum > 0.f) ? (msum / nsum) : 0.f;
        pm = 0.5f * (ratio + l);
    }
    float v = pm;
#pragma unroll
    for (int o = 16; o > 0; o >>= 1) v += __shfl_down_sync(0xffffffffu, v, o);
    if ((t & 31) == 0) wsum[t >> 5] = v;
    __syncthreads();
    if (t == 0) {
        float s = 0.f;
#pragma unroll
        for (int w = 0; w < 16; w++) s += wsum[w];
        out[b] = s / (float)vlen;
    }
}

// ============================================================
extern "C" void kernel_launch(void* const* d_in, const int* in_sizes, int n_in,
                              void* d_out, int out_size) {
    (void)in_sizes; (void)n_in; (void)out_size;
    const float* motion   = (const float*)d_in[0];
    const float* content  = (const float*)d_in[1];
    const float* distort  = (const float*)d_in[2];
    const int*   inlen    = (const int*)  d_in[3];
    const float* fc0w     = (const float*)d_in[4];
    const float* fc0b     = (const float*)d_in[5];
    const float* wih_f    = (const float*)d_in[6];
    const float* whh_f    = (const float*)d_in[7];
    const float* bih_f    = (const float*)d_in[8];
    const float* bhh_f    = (const float*)d_in[9];
    const float* wih_b    = (const float*)d_in[10];
    const float* whh_b    = (const float*)d_in[11];
    const float* bih_b    = (const float*)d_in[12];
    const float* bhh_b    = (const float*)d_in[13];
    const float* qw       = (const float*)d_in[14];
    const float* qb       = (const float*)d_in[15];
    const float* m1w      = (const float*)d_in[16];
    const float* m1b      = (const float*)d_in[17];
    const float* m2w      = (const float*)d_in[18];
    const float* m2b      = (const float*)d_in[19];
    float* out = (float*)d_out;

    cudaFuncSetAttribute(k_gemm1_mma, cudaFuncAttributeMaxDynamicSharedMemorySize, DYN_SMEM);

    k_prep_w<<<(REDn * DT + 255) / 256, 256>>>(fc0w);
    k_gemm1_mma<<<Mrows / MT, 512, DYN_SMEM>>>(content, distort, motion, fc0b, inlen);
    k_gemm2<<<dim3(Mrows / 128, 3), 256>>>(wih_f, wih_b, bih_f, bih_b, inlen);
    k_gru<<<dim3(Bn, 2), 32>>>(inlen, whh_f, whh_b, bhh_f, bhh_b);
    k_final<<<Bn, 512>>>(inlen, qw, qb, m1w, m1b, m2w, m2b, out);
}

// round 13
// speedup vs baseline: 1.4209x; 1.3230x over previous
#include <cuda_runtime.h>
#include <cuda_fp16.h>
#include <cstdint>

#define Bn   64
#define Tn   512
#define Hn   32
#define REDn 128
#define DC   4096
#define DD   512
#define DM   256
#define DT   4864
#define Mrows (Bn*Tn)   // 32768

#define KT    32              // fp16 K per tile
#define NKT   (DT/KT)         // 152 k-tiles
#define MT    256             // M rows per CTA

// -------- scratch (static __device__, no allocations) --------
__device__ float g_scores[(size_t)Mrows * REDn];          // 16 MB
__device__ float g_xg[(size_t)Mrows * 192];               // 24 MB
__device__ float g_outF[(size_t)Mrows * Hn];              // 4 MB
__device__ float g_outB[(size_t)Mrows * Hn];              // 4 MB
__device__ __half g_Wh[(size_t)REDn * DT];                // 1.25 MB (single fp16 W)

// ============================================================
// helpers
// ============================================================
__device__ __forceinline__ uint32_t smem_u32(const void* p) {
    uint32_t a;
    asm("{ .reg .u64 t; cvta.to.shared.u64 t, %1; cvt.u32.u64 %0, t; }" : "=r"(a) : "l"(p));
    return a;
}
__device__ __forceinline__ void cp16(uint32_t dst, const void* src) {
    asm volatile("cp.async.cg.shared.global [%0], [%1], 16;" :: "r"(dst), "l"(src) : "memory");
}
__device__ __forceinline__ void cp_commit() {
    asm volatile("cp.async.commit_group;" ::: "memory");
}
__device__ __forceinline__ void cp_wait3() {
    asm volatile("cp.async.wait_group 3;" ::: "memory");
}
__device__ __forceinline__ void ldsm_x4(uint32_t* r, uint32_t addr) {
    asm volatile("ldmatrix.sync.aligned.m8n8.x4.shared.b16 {%0,%1,%2,%3}, [%4];"
                 : "=r"(r[0]), "=r"(r[1]), "=r"(r[2]), "=r"(r[3]) : "r"(addr));
}
__device__ __forceinline__ void mma16816h(float* c, const uint32_t* a, const uint32_t* b) {
    asm volatile("mma.sync.aligned.m16n8k16.row.col.f32.f16.f16.f32 "
                 "{%0,%1,%2,%3}, {%4,%5,%6,%7}, {%8,%9}, {%0,%1,%2,%3};"
                 : "+f"(c[0]), "+f"(c[1]), "+f"(c[2]), "+f"(c[3])
                 : "r"(a[0]), "r"(a[1]), "r"(a[2]), "r"(a[3]), "r"(b[0]), "r"(b[1]));
}
// split float4 into fp16 hi pair-words and fp16 lo pair-words
__device__ __forceinline__ void split4h(float4 v, uint32_t& h01, uint32_t& h23,
                                        uint32_t& l01, uint32_t& l23) {
    __half hx = __float2half_rn(v.x);
    __half hy = __float2half_rn(v.y);
    __half hz = __float2half_rn(v.z);
    __half hw = __float2half_rn(v.w);
    float rx = v.x - __half2float(hx);
    float ry = v.y - __half2float(hy);
    float rz = v.z - __half2float(hz);
    float rw = v.w - __half2float(hw);
    __half2 H0 = __halves2half2(hx, hy);
    __half2 H1 = __halves2half2(hz, hw);
    __half2 L0 = __floats2half2_rn(rx, ry);
    __half2 L1 = __floats2half2_rn(rz, rw);
    h01 = *reinterpret_cast<uint32_t*>(&H0);
    h23 = *reinterpret_cast<uint32_t*>(&H1);
    l01 = *reinterpret_cast<uint32_t*>(&L0);
    l23 = *reinterpret_cast<uint32_t*>(&L1);
}
// packed dual-fp32 ops
__device__ __forceinline__ unsigned long long pack2(float x, float y) {
    unsigned long long r;
    asm("mov.b64 %0, {%1,%2};" : "=l"(r) : "f"(x), "f"(y));
    return r;
}
__device__ __forceinline__ unsigned long long ffma2(unsigned long long a,
                                                    unsigned long long b,
                                                    unsigned long long c) {
    unsigned long long d;
    asm("fma.rn.f32x2 %0, %1, %2, %3;" : "=l"(d) : "l"(a), "l"(b), "l"(c));
    return d;
}
__device__ __forceinline__ unsigned long long fadd2(unsigned long long a,
                                                    unsigned long long b) {
    unsigned long long d;
    asm("add.rn.f32x2 %0, %1, %2;" : "=l"(d) : "l"(a), "l"(b));
    return d;
}
__device__ __forceinline__ float2 unpack2(unsigned long long v) {
    float2 f;
    asm("mov.b64 {%0,%1}, %2;" : "=f"(f.x), "=f"(f.y) : "l"(v));
    return f;
}
__device__ __forceinline__ float rcp_fast(float x) {
    float y;
    asm("rcp.approx.f32 %0, %1;" : "=f"(y) : "f"(x));
    return y;
}
__device__ __forceinline__ float sigmoid_fast(float x) {
    return rcp_fast(1.f + __expf(-x));
}
__device__ __forceinline__ float tanh_fast(float x) {
    return __fmaf_rn(2.f, rcp_fast(1.f + __expf(-2.f * x)), -1.f);
}

// ============================================================
// Kernel 0: convert fc0_w to fp16 (single operand)
// ============================================================
__global__ void __launch_bounds__(256) k_prep_w(const float* __restrict__ W) {
    int i = blockIdx.x * 256 + threadIdx.x;
    if (i < REDn * DT) g_Wh[i] = __float2half_rn(W[i]);
}

// ============================================================
// Kernel 1: mma.sync fp16 2-product GEMM (A split hi/lo fp16, W single fp16).
// MT=256, 16 warps (4m x 4n), warp tile 64x32. A loaded to registers
// (LDG.128), split in regs, STS to A_hi/A_lo. W in 4-stage cp.async ring.
// Early exit per tile on vlen.
//
// SMEM (1024-aligned base):
//   [0     :20480)  A_hi fp16 [256 x 80B pad]
//   [20480 :40960)  A_lo
//   W ring stage s at 40960 + s*10240: [128 rows x 80B pad]
// ============================================================
#define SM_ABF_HI 0u
#define SM_ABF_LO 20480u
#define SM_WRING  40960u
#define WSTG      10240u
#define DYN_SMEM  (40960 + 4*10240 + 1024)   // 82944

__global__ void __launch_bounds__(512, 1) k_gemm1_mma(
    const float* __restrict__ content, const float* __restrict__ distort,
    const float* __restrict__ motion,  const float* __restrict__ bias,
    const int* __restrict__ inputLength)
{
    const int m0 = blockIdx.x * MT;
    {   // early exit: tile rows all >= vlen of this batch
        const int vlen = inputLength[m0 >> 9] - 9;
        if ((m0 & 511) >= vlen) return;
    }

    extern __shared__ char dynsmem[];
    __shared__ float s_bias[128];

    const int tid = threadIdx.x;
    const int wid = tid >> 5;
    const int lid = tid & 31;
    const int wm  = wid & 3;     // 4 m-warps x 64 rows
    const int wn  = wid >> 2;    // 4 n-warps x 32 cols

    const uint32_t raw  = smem_u32(dynsmem);
    const uint32_t base = (raw + 1023u) & ~1023u;
    char* sm = dynsmem + (base - raw);

    if (tid < 128) s_bias[tid] = bias[tid];

    // W cp assignment: 512 threads = 128 rows x 4 chunks of 16B
    const int hrow = tid >> 2;
    const int jw   = tid & 3;

    // A chunk constants
    const int ar0 = tid >> 3;    // row for i=0 (rows step +64 per i)
    const int aj  = tid & 7;

    const uint32_t aoff = (uint32_t)((wm * 64 + (lid & 15)) * 80 + ((lid >> 4) << 4));
    const int g3 = lid >> 3;
    const uint32_t brow_off = (uint32_t)(((g3 >> 1) << 3) + (lid & 7));
    const uint32_t bk_off   = (uint32_t)((g3 & 1) * 16);

    float acc[4][4][4];
#pragma unroll
    for (int i = 0; i < 4; i++)
#pragma unroll
        for (int j = 0; j < 4; j++)
#pragma unroll
            for (int k = 0; k < 4; k++) acc[i][j][k] = 0.f;

    float4 areg[4];

    auto load_a = [&](int c) {
        if (c < NKT) {
            const int kt = c * KT;
            const float* asrc; int astr, koff;
            if (kt < DC)           { asrc = content; astr = DC; koff = kt; }
            else if (kt < DC + DD) { asrc = distort; astr = DD; koff = kt - DC; }
            else                   { asrc = motion;  astr = DM; koff = kt - DC - DD; }
#pragma unroll
            for (int i = 0; i < 4; ++i) {
                int r = ar0 + i * 64;
                areg[i] = *reinterpret_cast<const float4*>(
                    asrc + (size_t)(m0 + r) * astr + koff + aj * 4);
            }
        }
    };

    auto issue_w = [&](int c) {
        if (c < NKT) {
            const int kt = c * KT;
            const uint32_t wb = base + SM_WRING + (uint32_t)(c & 3) * WSTG;
            cp16(wb + (uint32_t)(hrow * 80 + jw * 16),
                 (const char*)g_Wh + ((size_t)hrow * DT + kt) * 2 + jw * 16);
        }
        cp_commit();
    };

    // prologue
    load_a(0);
    issue_w(0);
    issue_w(1);
    issue_w(2);

    for (int c = 0; c < NKT; ++c) {
        __syncthreads();   // all warps done reading A_bf(c-1) and W stage (c+3)&3

        // split A(c) from registers -> A_hi / A_lo fp16 (padded rows)
        // Each float4 = 4 floats -> 2 uint32 hi-pairs + 2 uint32 lo-pairs,
        // but aj indexes 4-float chunks: each thread writes 8B to hi, 8B to lo.
#pragma unroll
        for (int i = 0; i < 4; ++i) {
            int r = ar0 + i * 64;
            uint32_t h01, h23, l01, l23;
            split4h(areg[i], h01, h23, l01, l23);
            *reinterpret_cast<uint2*>(sm + SM_ABF_HI + r * 80 + aj * 8) = make_uint2(h01, h23);
            *reinterpret_cast<uint2*>(sm + SM_ABF_LO + r * 80 + aj * 8) = make_uint2(l01, l23);
        }
        load_a(c + 1);     // LDG for next tile
        issue_w(c + 3);    // W ring stays 3 stages ahead
        cp_wait3();        // W(c) resident
        __syncthreads();   // A(c) visible

        const uint32_t wbh = base + SM_WRING + (uint32_t)(c & 3) * WSTG;
#pragma unroll
        for (int ks = 0; ks < 2; ks++) {
            const uint32_t akb = base + SM_ABF_HI + aoff + (uint32_t)(ks * 32);
            uint32_t ah[4][4], al[4][4], bb[4][2];
#pragma unroll
            for (int mf = 0; mf < 4; mf++) ldsm_x4(ah[mf], akb + (uint32_t)(mf * 1280));
#pragma unroll
            for (int p = 0; p < 2; p++) {
                uint32_t r4[4];
                uint32_t addr = wbh + (uint32_t)((wn * 32 + p * 16 + brow_off) * 80)
                                    + bk_off + (uint32_t)(ks * 32);
                ldsm_x4(r4, addr);
                bb[2*p][0] = r4[0]; bb[2*p][1] = r4[1];
                bb[2*p+1][0] = r4[2]; bb[2*p+1][1] = r4[3];
            }
#pragma unroll
            for (int mf = 0; mf < 4; mf++)
#pragma unroll
                for (int nf = 0; nf < 4; nf++) mma16816h(acc[mf][nf], ah[mf], bb[nf]);
#pragma unroll
            for (int mf = 0; mf < 4; mf++) ldsm_x4(al[mf], akb + 20480u + (uint32_t)(mf * 1280));
#pragma unroll
            for (int mf = 0; mf < 4; mf++)
#pragma unroll
                for (int nf = 0; nf < 4; nf++) mma16816h(acc[mf][nf], al[mf], bb[nf]);
        }
    }

    {
        const int gq = lid >> 2;
        const int t4 = lid & 3;
#pragma unroll
        for (int mf = 0; mf < 4; mf++) {
            const int row0 = m0 + wm * 64 + mf * 16 + gq;
#pragma unroll
            for (int nf = 0; nf < 4; nf++) {
                const int col = wn * 32 + nf * 8 + 2 * t4;
                const float b0 = s_bias[col], b1 = s_bias[col + 1];
                float* p0 = g_scores + (size_t)row0 * REDn + col;
                float* p1 = g_scores + (size_t)(row0 + 8) * REDn + col;
                *reinterpret_cast<float2*>(p0) =
                    make_float2(acc[mf][nf][0] + b0, acc[mf][nf][1] + b1);
                *reinterpret_cast<float2*>(p1) =
                    make_float2(acc[mf][nf][2] + b0, acc[mf][nf][3] + b1);
            }
        }
    }
}

// ============================================================
// Kernel 2: xg[M,192] = scores @ [wih_f;wih_b]^T + bias (fp32 f32x2)
// with per-CTA early exit on vlen.
// ============================================================
__global__ void __launch_bounds__(256) k_gemm2(
    const float* __restrict__ wih_f, const float* __restrict__ wih_b,
    const float* __restrict__ bih_f, const float* __restrict__ bih_b,
    const int* __restrict__ inputLength)
{
    const int m0 = blockIdx.x * 128;
    {
        const int vlen = inputLength[m0 >> 9] - 9;
        if ((m0 & 511) >= vlen) return;
    }

    __shared__ float As[16][128];
    __shared__ float Bs[16][64];
    const int tid = threadIdx.x;
    const int n0  = blockIdx.y * 64;
    const int txn = tid & 15;
    const int tym = tid >> 4;

    unsigned long long acc[8][2];
#pragma unroll
    for (int i = 0; i < 8; i++) { acc[i][0] = 0ull; acc[i][1] = 0ull; }

    for (int kt = 0; kt < REDn; kt += 16) {
#pragma unroll
        for (int ld = 0; ld < 2; ld++) {
            int lin = tid + ld * 256;
            int row = lin >> 2;
            int k4  = lin & 3;
            float4 v = *reinterpret_cast<const float4*>(&g_scores[(size_t)(m0 + row) * REDn + kt + k4 * 4]);
            As[k4 * 4 + 0][row] = v.x;
            As[k4 * 4 + 1][row] = v.y;
            As[k4 * 4 + 2][row] = v.z;
            As[k4 * 4 + 3][row] = v.w;
        }
        {
            int n  = tid >> 2;
            int k4 = tid & 3;
            int ng = n0 + n;
            const float* src = (ng < 96) ? (wih_f + (size_t)ng * REDn)
                                         : (wih_b + (size_t)(ng - 96) * REDn);
            float4 v = *reinterpret_cast<const float4*>(src + kt + k4 * 4);
            Bs[k4 * 4 + 0][n] = v.x;
            Bs[k4 * 4 + 1][n] = v.y;
            Bs[k4 * 4 + 2][n] = v.z;
            Bs[k4 * 4 + 3][n] = v.w;
        }
        __syncthreads();
#pragma unroll
        for (int kk = 0; kk < 16; kk++) {
            float4 a0 = *reinterpret_cast<const float4*>(&As[kk][tym * 8]);
            float4 a1 = *reinterpret_cast<const float4*>(&As[kk][tym * 8 + 4]);
            unsigned long long b0 = *reinterpret_cast<const unsigned long long*>(&Bs[kk][txn * 4]);
            unsigned long long b1 = *reinterpret_cast<const unsigned long long*>(&Bs[kk][txn * 4 + 2]);
            float avv[8] = {a0.x, a0.y, a0.z, a0.w, a1.x, a1.y, a1.z, a1.w};
#pragma unroll
            for (int i = 0; i < 8; i++) {
                unsigned long long ap = pack2(avv[i], avv[i]);
                acc[i][0] = ffma2(ap, b0, acc[i][0]);
                acc[i][1] = ffma2(ap, b1, acc[i][1]);
            }
        }
        __syncthreads();
    }
    const int nb = n0 + txn * 4;
    float bv[4];
#pragma unroll
    for (int jj = 0; jj < 4; jj++) {
        int ngj = nb + jj;
        bv[jj] = (ngj < 96) ? bih_f[ngj] : bih_b[ngj - 96];
    }
#pragma unroll
    for (int i = 0; i < 8; i++) {
        int mg = m0 + tym * 8 + i;
        float2 f0 = unpack2(acc[i][0]);
        float2 f1 = unpack2(acc[i][1]);
        *reinterpret_cast<float4*>(&g_xg[(size_t)mg * 192 + nb]) =
            make_float4(f0.x + bv[0], f0.y + bv[1], f1.x + bv[2], f1.y + bv[3]);
    }
}

// ============================================================
// Kernel 3: masked GRU — one warp per (batch, direction), loop to vlen.
// TRUE prefetch depth 6 (register ring, unroll x6); rcp.approx activations.
// ============================================================
__global__ void __launch_bounds__(32) k_gru(
    const int*   __restrict__ inputLength,
    const float* __restrict__ whh_f, const float* __restrict__ whh_b,
    const float* __restrict__ bhh_f, const float* __restrict__ bhh_b)
{
    const int b   = blockIdx.x;
    const int dir = blockIdx.y;
    const int j   = threadIdx.x;   // 0..31

    const float* whh = dir ? whh_b : whh_f;
    const float* bhh = dir ? bhh_b : bhh_f;

    unsigned long long wr[16], wz[16], wn2[16];
    const float2* wrp = reinterpret_cast<const float2*>(whh + j * 32);
    const float2* wzp = reinterpret_cast<const float2*>(whh + (32 + j) * 32);
    const float2* wnp = reinterpret_cast<const float2*>(whh + (64 + j) * 32);
#pragma unroll
    for (int i = 0; i < 16; i++) {
        float2 a = wrp[i], cz = wzp[i], d = wnp[i];
        wr[i]  = pack2(a.x, a.y);
        wz[i]  = pack2(cz.x, cz.y);
        wn2[i] = pack2(d.x, d.y);
    }
    const float br = bhh[j], bz = bhh[32 + j], bn = bhh[64 + j];

    __shared__ __align__(16) float sh[2][32];

    const int vlen = inputLength[b] - 9;   // >= 191
    float* outp = (dir ? g_outB : g_outF) + (size_t)b * Tn * Hn + j;
    const float* xgbase = g_xg + (size_t)b * Tn * 192 + dir * 96;

    // register ring: 6 sets (vlen >= 191 >> 6, all preloads valid)
    float xr0,xz0,xn0, xr1,xz1,xn1, xr2,xz2,xn2, xr3,xz3,xn3, xr4,xz4,xn4, xr5,xz5,xn5;
#define PRELOAD(K, XR, XZ, XN)                                                \
    {                                                                         \
        const float* x = xgbase + (size_t)(dir ? (vlen - 1 - (K)) : (K)) * 192; \
        XR = x[j]; XZ = x[32 + j]; XN = x[64 + j];                            \
    }
    PRELOAD(0, xr0, xz0, xn0)
    PRELOAD(1, xr1, xz1, xn1)
    PRELOAD(2, xr2, xz2, xn2)
    PRELOAD(3, xr3, xz3, xn3)
    PRELOAD(4, xr4, xz4, xn4)
    PRELOAD(5, xr5, xz5, xn5)
#undef PRELOAD

    float h = 0.f;
    int s = 0;

#define GRU_STEP(XR, XZ, XN)                                                  \
    {                                                                         \
        const float cxr = XR, cxz = XZ, cxn = XN;                             \
        const int sp = s + 6;                                                 \
        if (sp < vlen) {                                                      \
            const float* x = xgbase + (size_t)(dir ? (vlen - 1 - sp) : sp) * 192; \
            XR = x[j]; XZ = x[32 + j]; XN = x[64 + j];                        \
        }                                                                     \
        sh[s & 1][j] = h;                                                     \
        __syncwarp();                                                         \
        const unsigned long long* hp =                                        \
            reinterpret_cast<const unsigned long long*>(&sh[s & 1][0]);       \
        unsigned long long ar0 = 0ull, ar1 = 0ull;                            \
        unsigned long long az0 = 0ull, az1 = 0ull;                            \
        unsigned long long an0 = 0ull, an1 = 0ull;                            \
        _Pragma("unroll")                                                     \
        for (int i = 0; i < 16; i += 2) {                                     \
            unsigned long long hv0 = hp[i];                                   \
            unsigned long long hv1 = hp[i + 1];                               \
            ar0 = ffma2(hv0, wr[i],      ar0);                                \
            ar1 = ffma2(hv1, wr[i + 1],  ar1);                                \
            az0 = ffma2(hv0, wz[i],      az0);                                \
            az1 = ffma2(hv1, wz[i + 1],  az1);                                \
            an0 = ffma2(hv0, wn2[i],     an0);                                \
            an1 = ffma2(hv1, wn2[i + 1], an1);                                \
        }                                                                     \
        float2 fr = unpack2(fadd2(ar0, ar1));                                 \
        float2 fz = unpack2(fadd2(az0, az1));                                 \
        float2 fn = unpack2(fadd2(an0, an1));                                 \
        float hgr = fr.x + fr.y + br;                                         \
        float hgz = fz.x + fz.y + bz;                                         \
        float hgn = fn.x + fn.y + bn;                                         \
        float r  = sigmoid_fast(cxr + hgr);                                   \
        float z  = sigmoid_fast(cxz + hgz);                                   \
        float nn = tanh_fast(__fmaf_rn(r, hgn, cxn));                         \
        h = __fmaf_rn(z, h - nn, nn);                                         \
        int tout = dir ? (vlen - 1 - s) : s;                                  \
        outp[(size_t)tout * Hn] = h;                                          \
        s++;                                                                  \
    }

    while (s + 6 <= vlen) {
        GRU_STEP(xr0, xz0, xn0)
        GRU_STEP(xr1, xz1, xn1)
        GRU_STEP(xr2, xz2, xn2)
        GRU_STEP(xr3, xz3, xn3)
        GRU_STEP(xr4, xz4, xn4)
        GRU_STEP(xr5, xz5, xn5)
    }
    if (s < vlen) GRU_STEP(xr0, xz0, xn0)
    if (s < vlen) GRU_STEP(xr1, xz1, xn1)
    if (s < vlen) GRU_STEP(xr2, xz2, xn2)
    if (s < vlen) GRU_STEP(xr3, xz3, xn3)
    if (s < vlen) GRU_STEP(xr4, xz4, xn4)
#undef GRU_STEP
}

// ============================================================
// Kernel 4: q projection + MLP + argmax-selected TP score.
// ============================================================
__global__ void __launch_bounds__(512) k_final(
    const int*   __restrict__ inputLength,
    const float* __restrict__ qw,  const float* __restrict__ qb,
    const float* __restrict__ m1w, const float* __restrict__ m1b,
    const float* __restrict__ m2w, const float* __restrict__ m2b,
    float* __restrict__ out)
{
    const int b = blockIdx.x;
    const int t = threadIdx.x;
    __shared__ float sq[512];
    __shared__ float sh1[32];
    __shared__ int   s_tau;
    __shared__ float wsum[16];

    const int vlen = inputLength[b] - 9;

    float qv = 0.f;
    if (t < vlen) {
        const float* of = g_outF + ((size_t)b * Tn + t) * Hn;
        const float* ob = g_outB + ((size_t)b * Tn + t) * Hn;
        float a = qb[0];
#pragma unroll
        for (int jj = 0; jj < 32; jj++) a += of[jj] * qw[jj] + ob[jj] * qw[32 + jj];
        qv = a;
    }
    sq[t] = qv;
    __syncthreads();

    if (t < 32) {
        const float* lf = g_outF + ((size_t)b * Tn + (vlen - 1)) * Hn;
        const float* lb = g_outB + ((size_t)b * Tn) * Hn;
        float a = m1b[t];
#pragma unroll
        for (int jj = 0; jj < 32; jj++) a += lf[jj] * m1w[t * 64 + jj] + lb[jj] * m1w[t * 64 + 32 + jj];
        sh1[t] = fmaxf(a, 0.f);
    }
    __syncthreads();
    if (t == 0) {
        float best = -3.0e38f; int bi = 0;
#pragma unroll
        for (int c = 0; c < 5; c++) {
            float v = m2b[c];
#pragma unroll
            for (int o = 0; o < 32; o++) v += sh1[o] * m2w[c * 32 + o];
            if (v > best) { best = v; bi = c; }
        }
        s_tau = 8 + 2 * bi;
    }
    __syncthreads();

    const int tau = s_tau;
    float pm = 0.f;
    if (t < vlen) {
        float l = 3.0e38f;
        for (int k = 0; k < tau; k++) {
            int idx = t - k;
            float v = (idx >= 0) ? sq[idx] : 3.0e38f;
            l = fminf(l, v);
        }
        float msum = 0.f, nsum = 0.f;
        for (int k = 0; k < tau; k++) {
            int idx = t + k;
            if (idx < vlen) {
                float w = __expf(-sq[idx]);
                nsum += w;
                msum += sq[idx] * w;
            }
        }
        float ratio = (nsum > 0.f) ? (msum / nsum) : 0.f;
        pm = 0.5f * (ratio + l);
    }
    float v = pm;
#pragma unroll
    for (int o = 16; o > 0; o >>= 1) v += __shfl_down_sync(0xffffffffu, v, o);
    if ((t & 31) == 0) wsum[t >> 5] = v;
    __syncthreads();
    if (t == 0) {
        float s = 0.f;
#pragma unroll
        for (int w = 0; w < 16; w++) s += wsum[w];
        out[b] = s / (float)vlen;
    }
}

// ============================================================
extern "C" void kernel_launch(void* const* d_in, const int* in_sizes, int n_in,
                              void* d_out, int out_size) {
    (void)in_sizes; (void)n_in; (void)out_size;
    const float* motion   = (const float*)d_in[0];
    const float* content  = (const float*)d_in[1];
    const float* distort  = (const float*)d_in[2];
    const int*   inlen    = (const int*)  d_in[3];
    const float* fc0w     = (const float*)d_in[4];
    const float* fc0b     = (const float*)d_in[5];
    const float* wih_f    = (const float*)d_in[6];
    const float* whh_f    = (const float*)d_in[7];
    const float* bih_f    = (const float*)d_in[8];
    const float* bhh_f    = (const float*)d_in[9];
    const float* wih_b    = (const float*)d_in[10];
    const float* whh_b    = (const float*)d_in[11];
    const float* bih_b    = (const float*)d_in[12];
    const float* bhh_b    = (const float*)d_in[13];
    const float* qw       = (const float*)d_in[14];
    const float* qb       = (const float*)d_in[15];
    const float* m1w      = (const float*)d_in[16];
    const float* m1b      = (const float*)d_in[17];
    const float* m2w      = (const float*)d_in[18];
    const float* m2b      = (const float*)d_in[19];
    float* out = (float*)d_out;

    cudaFuncSetAttribute(k_gemm1_mma, cudaFuncAttributeMaxDynamicSharedMemorySize, DYN_SMEM);

    k_prep_w<<<(REDn * DT + 255) / 256, 256>>>(fc0w);
    k_gemm1_mma<<<Mrows / MT, 512, DYN_SMEM>>>(content, distort, motion, fc0b, inlen);
    k_gemm2<<<dim3(Mrows / 128, 3), 256>>>(wih_f, wih_b, bih_f, bih_b, inlen);
    k_gru<<<dim3(Bn, 2), 32>>>(inlen, whh_f, whh_b, bhh_f, bhh_b);
    k_final<<<Bn, 512>>>(inlen, qw, qb, m1w, m1b, m2w, m2b, out);
}

// round 14
// speedup vs baseline: 1.8168x; 1.2786x over previous
#include <cuda_runtime.h>
#include <cuda_fp16.h>
#include <cstdint>

#define Bn   64
#define Tn   512
#define Hn   32
#define REDn 128
#define DC   4096
#define DD   512
#define DM   256
#define DT   4864
#define Mrows (Bn*Tn)   // 32768

#define KT    32              // fp16 K per tile
#define NKT   (DT/KT)         // 152 k-tiles
#define MT    256             // M rows per CTA

// -------- scratch (static __device__, no allocations) --------
__device__ float g_scores[(size_t)Mrows * REDn];          // 16 MB
__device__ float g_xg[(size_t)Mrows * 192];               // 24 MB
__device__ float g_outF[(size_t)Mrows * Hn];              // 4 MB
__device__ float g_outB[(size_t)Mrows * Hn];              // 4 MB
__device__ __half g_Wh[(size_t)REDn * DT];                // 1.25 MB (single fp16 W)

// ============================================================
// helpers
// ============================================================
__device__ __forceinline__ uint32_t smem_u32(const void* p) {
    uint32_t a;
    asm("{ .reg .u64 t; cvta.to.shared.u64 t, %1; cvt.u32.u64 %0, t; }" : "=r"(a) : "l"(p));
    return a;
}
__device__ __forceinline__ void cp16(uint32_t dst, const void* src) {
    asm volatile("cp.async.cg.shared.global [%0], [%1], 16;" :: "r"(dst), "l"(src) : "memory");
}
__device__ __forceinline__ void cp_commit() {
    asm volatile("cp.async.commit_group;" ::: "memory");
}
__device__ __forceinline__ void cp_wait3() {
    asm volatile("cp.async.wait_group 3;" ::: "memory");
}
__device__ __forceinline__ void ldsm_x4(uint32_t* r, uint32_t addr) {
    asm volatile("ldmatrix.sync.aligned.m8n8.x4.shared.b16 {%0,%1,%2,%3}, [%4];"
                 : "=r"(r[0]), "=r"(r[1]), "=r"(r[2]), "=r"(r[3]) : "r"(addr));
}
__device__ __forceinline__ void mma16816h(float* c, const uint32_t* a, const uint32_t* b) {
    asm volatile("mma.sync.aligned.m16n8k16.row.col.f32.f16.f16.f32 "
                 "{%0,%1,%2,%3}, {%4,%5,%6,%7}, {%8,%9}, {%0,%1,%2,%3};"
                 : "+f"(c[0]), "+f"(c[1]), "+f"(c[2]), "+f"(c[3])
                 : "r"(a[0]), "r"(a[1]), "r"(a[2]), "r"(a[3]), "r"(b[0]), "r"(b[1]));
}
// convert float4 -> two packed fp16 pair-words
__device__ __forceinline__ void cvt4h(float4 v, uint32_t& h01, uint32_t& h23) {
    __half2 H0 = __floats2half2_rn(v.x, v.y);
    __half2 H1 = __floats2half2_rn(v.z, v.w);
    h01 = *reinterpret_cast<uint32_t*>(&H0);
    h23 = *reinterpret_cast<uint32_t*>(&H1);
}
// packed dual-fp32 ops
__device__ __forceinline__ unsigned long long pack2(float x, float y) {
    unsigned long long r;
    asm("mov.b64 %0, {%1,%2};" : "=l"(r) : "f"(x), "f"(y));
    return r;
}
__device__ __forceinline__ unsigned long long ffma2(unsigned long long a,
                                                    unsigned long long b,
                                                    unsigned long long c) {
    unsigned long long d;
    asm("fma.rn.f32x2 %0, %1, %2, %3;" : "=l"(d) : "l"(a), "l"(b), "l"(c));
    return d;
}
__device__ __forceinline__ unsigned long long fadd2(unsigned long long a,
                                                    unsigned long long b) {
    unsigned long long d;
    asm("add.rn.f32x2 %0, %1, %2;" : "=l"(d) : "l"(a), "l"(b));
    return d;
}
__device__ __forceinline__ float2 unpack2(unsigned long long v) {
    float2 f;
    asm("mov.b64 {%0,%1}, %2;" : "=f"(f.x), "=f"(f.y) : "l"(v));
    return f;
}
__device__ __forceinline__ float rcp_fast(float x) {
    float y;
    asm("rcp.approx.f32 %0, %1;" : "=f"(y) : "f"(x));
    return y;
}
__device__ __forceinline__ float sigmoid_fast(float x) {
    return rcp_fast(1.f + __expf(-x));
}
__device__ __forceinline__ float tanh_fast(float x) {
    return __fmaf_rn(2.f, rcp_fast(1.f + __expf(-2.f * x)), -1.f);
}

// ============================================================
// Kernel 0: convert fc0_w to fp16 (single operand)
// ============================================================
__global__ void __launch_bounds__(256) k_prep_w(const float* __restrict__ W) {
    int i = blockIdx.x * 256 + threadIdx.x;
    if (i < REDn * DT) g_Wh[i] = __float2half_rn(W[i]);
}

// ============================================================
// Kernel 1: mma.sync fp16 SINGLE-product GEMM (A fp16, W fp16).
// MT=256, 16 warps (4m x 4n), warp tile 64x32. A loaded to registers
// (LDG.128), converted in regs, STS to A_h. W in 4-stage cp.async ring.
// Early exit per tile on vlen.
//
// SMEM (1024-aligned base):
//   [0     :20480)  A_h fp16 [256 x 80B pad]
//   W ring stage s at 20480 + s*10240: [128 rows x 80B pad]
// ============================================================
#define SM_ABF    0u
#define SM_WRING  20480u
#define WSTG      10240u
#define DYN_SMEM  (20480 + 4*10240 + 1024)   // 62464

__global__ void __launch_bounds__(512, 1) k_gemm1_mma(
    const float* __restrict__ content, const float* __restrict__ distort,
    const float* __restrict__ motion,  const float* __restrict__ bias,
    const int* __restrict__ inputLength)
{
    const int m0 = blockIdx.x * MT;
    {   // early exit: tile rows all >= vlen of this batch
        const int vlen = inputLength[m0 >> 9] - 9;
        if ((m0 & 511) >= vlen) return;
    }

    extern __shared__ char dynsmem[];
    __shared__ float s_bias[128];

    const int tid = threadIdx.x;
    const int wid = tid >> 5;
    const int lid = tid & 31;
    const int wm  = wid & 3;     // 4 m-warps x 64 rows
    const int wn  = wid >> 2;    // 4 n-warps x 32 cols

    const uint32_t raw  = smem_u32(dynsmem);
    const uint32_t base = (raw + 1023u) & ~1023u;
    char* sm = dynsmem + (base - raw);

    if (tid < 128) s_bias[tid] = bias[tid];

    // W cp assignment: 512 threads = 128 rows x 4 chunks of 16B
    const int hrow = tid >> 2;
    const int jw   = tid & 3;

    // A chunk constants
    const int ar0 = tid >> 3;    // row for i=0 (rows step +64 per i)
    const int aj  = tid & 7;

    const uint32_t aoff = (uint32_t)((wm * 64 + (lid & 15)) * 80 + ((lid >> 4) << 4));
    const int g3 = lid >> 3;
    const uint32_t brow_off = (uint32_t)(((g3 >> 1) << 3) + (lid & 7));
    const uint32_t bk_off   = (uint32_t)((g3 & 1) * 16);

    float acc[4][4][4];
#pragma unroll
    for (int i = 0; i < 4; i++)
#pragma unroll
        for (int j = 0; j < 4; j++)
#pragma unroll
            for (int k = 0; k < 4; k++) acc[i][j][k] = 0.f;

    float4 areg[4];

    auto load_a = [&](int c) {
        if (c < NKT) {
            const int kt = c * KT;
            const float* asrc; int astr, koff;
            if (kt < DC)           { asrc = content; astr = DC; koff = kt; }
            else if (kt < DC + DD) { asrc = distort; astr = DD; koff = kt - DC; }
            else                   { asrc = motion;  astr = DM; koff = kt - DC - DD; }
#pragma unroll
            for (int i = 0; i < 4; ++i) {
                int r = ar0 + i * 64;
                areg[i] = *reinterpret_cast<const float4*>(
                    asrc + (size_t)(m0 + r) * astr + koff + aj * 4);
            }
        }
    };

    auto issue_w = [&](int c) {
        if (c < NKT) {
            const int kt = c * KT;
            const uint32_t wb = base + SM_WRING + (uint32_t)(c & 3) * WSTG;
            cp16(wb + (uint32_t)(hrow * 80 + jw * 16),
                 (const char*)g_Wh + ((size_t)hrow * DT + kt) * 2 + jw * 16);
        }
        cp_commit();
    };

    // prologue
    load_a(0);
    issue_w(0);
    issue_w(1);
    issue_w(2);

    for (int c = 0; c < NKT; ++c) {
        __syncthreads();   // all warps done reading A(c-1) and W stage (c+3)&3

        // convert A(c) from registers -> A_h fp16 (padded rows)
#pragma unroll
        for (int i = 0; i < 4; ++i) {
            int r = ar0 + i * 64;
            uint32_t h01, h23;
            cvt4h(areg[i], h01, h23);
            *reinterpret_cast<uint2*>(sm + SM_ABF + r * 80 + aj * 8) = make_uint2(h01, h23);
        }
        load_a(c + 1);     // LDG for next tile
        issue_w(c + 3);    // W ring stays 3 stages ahead
        cp_wait3();        // W(c) resident
        __syncthreads();   // A(c) visible

        const uint32_t wbh = base + SM_WRING + (uint32_t)(c & 3) * WSTG;
#pragma unroll
        for (int ks = 0; ks < 2; ks++) {
            const uint32_t akb = base + SM_ABF + aoff + (uint32_t)(ks * 32);
            uint32_t ah[4][4], bb[4][2];
#pragma unroll
            for (int mf = 0; mf < 4; mf++) ldsm_x4(ah[mf], akb + (uint32_t)(mf * 1280));
#pragma unroll
            for (int p = 0; p < 2; p++) {
                uint32_t r4[4];
                uint32_t addr = wbh + (uint32_t)((wn * 32 + p * 16 + brow_off) * 80)
                                    + bk_off + (uint32_t)(ks * 32);
                ldsm_x4(r4, addr);
                bb[2*p][0] = r4[0]; bb[2*p][1] = r4[1];
                bb[2*p+1][0] = r4[2]; bb[2*p+1][1] = r4[3];
            }
#pragma unroll
            for (int mf = 0; mf < 4; mf++)
#pragma unroll
                for (int nf = 0; nf < 4; nf++) mma16816h(acc[mf][nf], ah[mf], bb[nf]);
        }
    }

    {
        const int gq = lid >> 2;
        const int t4 = lid & 3;
#pragma unroll
        for (int mf = 0; mf < 4; mf++) {
            const int row0 = m0 + wm * 64 + mf * 16 + gq;
#pragma unroll
            for (int nf = 0; nf < 4; nf++) {
                const int col = wn * 32 + nf * 8 + 2 * t4;
                const float b0 = s_bias[col], b1 = s_bias[col + 1];
                float* p0 = g_scores + (size_t)row0 * REDn + col;
                float* p1 = g_scores + (size_t)(row0 + 8) * REDn + col;
                *reinterpret_cast<float2*>(p0) =
                    make_float2(acc[mf][nf][0] + b0, acc[mf][nf][1] + b1);
                *reinterpret_cast<float2*>(p1) =
                    make_float2(acc[mf][nf][2] + b0, acc[mf][nf][3] + b1);
            }
        }
    }
}

// ============================================================
// Kernel 2: xg[M,192] = scores @ [wih_f;wih_b]^T + bias (fp32 f32x2)
// with per-CTA early exit on vlen.
// ============================================================
__global__ void __launch_bounds__(256) k_gemm2(
    const float* __restrict__ wih_f, const float* __restrict__ wih_b,
    const float* __restrict__ bih_f, const float* __restrict__ bih_b,
    const int* __restrict__ inputLength)
{
    const int m0 = blockIdx.x * 128;
    {
        const int vlen = inputLength[m0 >> 9] - 9;
        if ((m0 & 511) >= vlen) return;
    }

    __shared__ float As[16][128];
    __shared__ float Bs[16][64];
    const int tid = threadIdx.x;
    const int n0  = blockIdx.y * 64;
    const int txn = tid & 15;
    const int tym = tid >> 4;

    unsigned long long acc[8][2];
#pragma unroll
    for (int i = 0; i < 8; i++) { acc[i][0] = 0ull; acc[i][1] = 0ull; }

    for (int kt = 0; kt < REDn; kt += 16) {
#pragma unroll
        for (int ld = 0; ld < 2; ld++) {
            int lin = tid + ld * 256;
            int row = lin >> 2;
            int k4  = lin & 3;
            float4 v = *reinterpret_cast<const float4*>(&g_scores[(size_t)(m0 + row) * REDn + kt + k4 * 4]);
            As[k4 * 4 + 0][row] = v.x;
            As[k4 * 4 + 1][row] = v.y;
            As[k4 * 4 + 2][row] = v.z;
            As[k4 * 4 + 3][row] = v.w;
        }
        {
            int n  = tid >> 2;
            int k4 = tid & 3;
            int ng = n0 + n;
            const float* src = (ng < 96) ? (wih_f + (size_t)ng * REDn)
                                         : (wih_b + (size_t)(ng - 96) * REDn);
            float4 v = *reinterpret_cast<const float4*>(src + kt + k4 * 4);
            Bs[k4 * 4 + 0][n] = v.x;
            Bs[k4 * 4 + 1][n] = v.y;
            Bs[k4 * 4 + 2][n] = v.z;
            Bs[k4 * 4 + 3][n] = v.w;
        }
        __syncthreads();
#pragma unroll
        for (int kk = 0; kk < 16; kk++) {
            float4 a0 = *reinterpret_cast<const float4*>(&As[kk][tym * 8]);
            float4 a1 = *reinterpret_cast<const float4*>(&As[kk][tym * 8 + 4]);
            unsigned long long b0 = *reinterpret_cast<const unsigned long long*>(&Bs[kk][txn * 4]);
            unsigned long long b1 = *reinterpret_cast<const unsigned long long*>(&Bs[kk][txn * 4 + 2]);
            float avv[8] = {a0.x, a0.y, a0.z, a0.w, a1.x, a1.y, a1.z, a1.w};
#pragma unroll
            for (int i = 0; i < 8; i++) {
                unsigned long long ap = pack2(avv[i], avv[i]);
                acc[i][0] = ffma2(ap, b0, acc[i][0]);
                acc[i][1] = ffma2(ap, b1, acc[i][1]);
            }
        }
        __syncthreads();
    }
    const int nb = n0 + txn * 4;
    float bv[4];
#pragma unroll
    for (int jj = 0; jj < 4; jj++) {
        int ngj = nb + jj;
        bv[jj] = (ngj < 96) ? bih_f[ngj] : bih_b[ngj - 96];
    }
#pragma unroll
    for (int i = 0; i < 8; i++) {
        int mg = m0 + tym * 8 + i;
        float2 f0 = unpack2(acc[i][0]);
        float2 f1 = unpack2(acc[i][1]);
        *reinterpret_cast<float4*>(&g_xg[(size_t)mg * 192 + nb]) =
            make_float4(f0.x + bv[0], f0.y + bv[1], f1.x + bv[2], f1.y + bv[3]);
    }
}

// ============================================================
// Kernel 3: masked GRU — one warp per (batch, direction), loop to vlen.
// TRUE prefetch depth 6 (register ring, unroll x6); rcp.approx activations.
// ============================================================
__global__ void __launch_bounds__(32) k_gru(
    const int*   __restrict__ inputLength,
    const float* __restrict__ whh_f, const float* __restrict__ whh_b,
    const float* __restrict__ bhh_f, const float* __restrict__ bhh_b)
{
    const int b   = blockIdx.x;
    const int dir = blockIdx.y;
    const int j   = threadIdx.x;   // 0..31

    const float* whh = dir ? whh_b : whh_f;
    const float* bhh = dir ? bhh_b : bhh_f;

    unsigned long long wr[16], wz[16], wn2[16];
    const float2* wrp = reinterpret_cast<const float2*>(whh + j * 32);
    const float2* wzp = reinterpret_cast<const float2*>(whh + (32 + j) * 32);
    const float2* wnp = reinterpret_cast<const float2*>(whh + (64 + j) * 32);
#pragma unroll
    for (int i = 0; i < 16; i++) {
        float2 a = wrp[i], cz = wzp[i], d = wnp[i];
        wr[i]  = pack2(a.x, a.y);
        wz[i]  = pack2(cz.x, cz.y);
        wn2[i] = pack2(d.x, d.y);
    }
    const float br = bhh[j], bz = bhh[32 + j], bn = bhh[64 + j];

    __shared__ __align__(16) float sh[2][32];

    const int vlen = inputLength[b] - 9;   // >= 191
    float* outp = (dir ? g_outB : g_outF) + (size_t)b * Tn * Hn + j;
    const float* xgbase = g_xg + (size_t)b * Tn * 192 + dir * 96;

    float xr0,xz0,xn0, xr1,xz1,xn1, xr2,xz2,xn2, xr3,xz3,xn3, xr4,xz4,xn4, xr5,xz5,xn5;
#define PRELOAD(K, XR, XZ, XN)                                                \
    {                                                                         \
        const float* x = xgbase + (size_t)(dir ? (vlen - 1 - (K)) : (K)) * 192; \
        XR = x[j]; XZ = x[32 + j]; XN = x[64 + j];                            \
    }
    PRELOAD(0, xr0, xz0, xn0)
    PRELOAD(1, xr1, xz1, xn1)
    PRELOAD(2, xr2, xz2, xn2)
    PRELOAD(3, xr3, xz3, xn3)
    PRELOAD(4, xr4, xz4, xn4)
    PRELOAD(5, xr5, xz5, xn5)
#undef PRELOAD

    float h = 0.f;
    int s = 0;

#define GRU_STEP(XR, XZ, XN)                                                  \
    {                                                                         \
        const float cxr = XR, cxz = XZ, cxn = XN;                             \
        const int sp = s + 6;                                                 \
        if (sp < vlen) {                                                      \
            const float* x = xgbase + (size_t)(dir ? (vlen - 1 - sp) : sp) * 192; \
            XR = x[j]; XZ = x[32 + j]; XN = x[64 + j];                        \
        }                                                                     \
        sh[s & 1][j] = h;                                                     \
        __syncwarp();                                                         \
        const unsigned long long* hp =                                        \
            reinterpret_cast<const unsigned long long*>(&sh[s & 1][0]);       \
        unsigned long long ar0 = 0ull, ar1 = 0ull;                            \
        unsigned long long az0 = 0ull, az1 = 0ull;                            \
        unsigned long long an0 = 0ull, an1 = 0ull;                            \
        _Pragma("unroll")                                                     \
        for (int i = 0; i < 16; i += 2) {                                     \
            unsigned long long hv0 = hp[i];                                   \
            unsigned long long hv1 = hp[i + 1];                               \
            ar0 = ffma2(hv0, wr[i],      ar0);                                \
            ar1 = ffma2(hv1, wr[i + 1],  ar1);                                \
            az0 = ffma2(hv0, wz[i],      az0);                                \
            az1 = ffma2(hv1, wz[i + 1],  az1);                                \
            an0 = ffma2(hv0, wn2[i],     an0);                                \
            an1 = ffma2(hv1, wn2[i + 1], an1);                                \
        }                                                                     \
        float2 fr = unpack2(fadd2(ar0, ar1));                                 \
        float2 fz = unpack2(fadd2(az0, az1));                                 \
        float2 fn = unpack2(fadd2(an0, an1));                                 \
        float hgr = fr.x + fr.y + br;                                         \
        float hgz = fz.x + fz.y + bz;                                         \
        float hgn = fn.x + fn.y + bn;                                         \
        float r  = sigmoid_fast(cxr + hgr);                                   \
        float z  = sigmoid_fast(cxz + hgz);                                   \
        float nn = tanh_fast(__fmaf_rn(r, hgn, cxn));                         \
        h = __fmaf_rn(z, h - nn, nn);                                         \
        int tout = dir ? (vlen - 1 - s) : s;                                  \
        outp[(size_t)tout * Hn] = h;                                          \
        s++;                                                                  \
    }

    while (s + 6 <= vlen) {
        GRU_STEP(xr0, xz0, xn0)
        GRU_STEP(xr1, xz1, xn1)
        GRU_STEP(xr2, xz2, xn2)
        GRU_STEP(xr3, xz3, xn3)
        GRU_STEP(xr4, xz4, xn4)
        GRU_STEP(xr5, xz5, xn5)
    }
    if (s < vlen) GRU_STEP(xr0, xz0, xn0)
    if (s < vlen) GRU_STEP(xr1, xz1, xn1)
    if (s < vlen) GRU_STEP(xr2, xz2, xn2)
    if (s < vlen) GRU_STEP(xr3, xz3, xn3)
    if (s < vlen) GRU_STEP(xr4, xz4, xn4)
#undef GRU_STEP
}

// ============================================================
// Kernel 4: q projection + MLP + argmax-selected TP score.
// ============================================================
__global__ void __launch_bounds__(512) k_final(
    const int*   __restrict__ inputLength,
    const float* __restrict__ qw,  const float* __restrict__ qb,
    const float* __restrict__ m1w, const float* __restrict__ m1b,
    const float* __restrict__ m2w, const float* __restrict__ m2b,
    float* __restrict__ out)
{
    const int b = blockIdx.x;
    const int t = threadIdx.x;
    __shared__ float sq[512];
    __shared__ float sh1[32];
    __shared__ int   s_tau;
    __shared__ float wsum[16];

    const int vlen = inputLength[b] - 9;

    float qv = 0.f;
    if (t < vlen) {
        const float* of = g_outF + ((size_t)b * Tn + t) * Hn;
        const float* ob = g_outB + ((size_t)b * Tn + t) * Hn;
        float a = qb[0];
#pragma unroll
        for (int jj = 0; jj < 32; jj++) a += of[jj] * qw[jj] + ob[jj] * qw[32 + jj];
        qv = a;
    }
    sq[t] = qv;
    __syncthreads();

    if (t < 32) {
        const float* lf = g_outF + ((size_t)b * Tn + (vlen - 1)) * Hn;
        const float* lb = g_outB + ((size_t)b * Tn) * Hn;
        float a = m1b[t];
#pragma unroll
        for (int jj = 0; jj < 32; jj++) a += lf[jj] * m1w[t * 64 + jj] + lb[jj] * m1w[t * 64 + 32 + jj];
        sh1[t] = fmaxf(a, 0.f);
    }
    __syncthreads();
    if (t == 0) {
        float best = -3.0e38f; int bi = 0;
#pragma unroll
        for (int c = 0; c < 5; c++) {
            float v = m2b[c];
#pragma unroll
            for (int o = 0; o < 32; o++) v += sh1[o] * m2w[c * 32 + o];
            if (v > best) { best = v; bi = c; }
        }
        s_tau = 8 + 2 * bi;
    }
    __syncthreads();

    const int tau = s_tau;
    float pm = 0.f;
    if (t < vlen) {
        float l = 3.0e38f;
        for (int k = 0; k < tau; k++) {
            int idx = t - k;
            float v = (idx >= 0) ? sq[idx] : 3.0e38f;
            l = fminf(l, v);
        }
        float msum = 0.f, nsum = 0.f;
        for (int k = 0; k < tau; k++) {
            int idx = t + k;
            if (idx < vlen) {
                float w = __expf(-sq[idx]);
                nsum += w;
                msum += sq[idx] * w;
            }
        }
        float ratio = (nsum > 0.f) ? (msum / nsum) : 0.f;
        pm = 0.5f * (ratio + l);
    }
    float v = pm;
#pragma unroll
    for (int o = 16; o > 0; o >>= 1) v += __shfl_down_sync(0xffffffffu, v, o);
    if ((t & 31) == 0) wsum[t >> 5] = v;
    __syncthreads();
    if (t == 0) {
        float s = 0.f;
#pragma unroll
        for (int w = 0; w < 16; w++) s += wsum[w];
        out[b] = s / (float)vlen;
    }
}

// ============================================================
extern "C" void kernel_launch(void* const* d_in, const int* in_sizes, int n_in,
                              void* d_out, int out_size) {
    (void)in_sizes; (void)n_in; (void)out_size;
    const float* motion   = (const float*)d_in[0];
    const float* content  = (const float*)d_in[1];
    const float* distort  = (const float*)d_in[2];
    const int*   inlen    = (const int*)  d_in[3];
    const float* fc0w     = (const float*)d_in[4];
    const float* fc0b     = (const float*)d_in[5];
    const float* wih_f    = (const float*)d_in[6];
    const float* whh_f    = (const float*)d_in[7];
    const float* bih_f    = (const float*)d_in[8];
    const float* bhh_f    = (const float*)d_in[9];
    const float* wih_b    = (const float*)d_in[10];
    const float* whh_b    = (const float*)d_in[11];
    const float* bih_b    = (const float*)d_in[12];
    const float* bhh_b    = (const float*)d_in[13];
    const float* qw       = (const float*)d_in[14];
    const float* qb       = (const float*)d_in[15];
    const float* m1w      = (const float*)d_in[16];
    const float* m1b      = (const float*)d_in[17];
    const float* m2w      = (const float*)d_in[18];
    const float* m2b      = (const float*)d_in[19];
    float* out = (float*)d_out;

    cudaFuncSetAttribute(k_gemm1_mma, cudaFuncAttributeMaxDynamicSharedMemorySize, DYN_SMEM);

    k_prep_w<<<(REDn * DT + 255) / 256, 256>>>(fc0w);
    k_gemm1_mma<<<Mrows / MT, 512, DYN_SMEM>>>(content, distort, motion, fc0b, inlen);
    k_gemm2<<<dim3(Mrows / 128, 3), 256>>>(wih_f, wih_b, bih_f, bih_b, inlen);
    k_gru<<<dim3(Bn, 2), 32>>>(inlen, whh_f, whh_b, bhh_f, bhh_b);
    k_final<<<Bn, 512>>>(inlen, qw, qb, m1w, m1b, m2w, m2b, out);
}

// round 16
// speedup vs baseline: 1.9313x; 1.0630x over previous
#include <cuda_runtime.h>
#include <cuda_fp16.h>
#include <cstdint>

#define Bn   64
#define Tn   512
#define Hn   32
#define REDn 128
#define DC   4096
#define DD   512
#define DM   256
#define DT   4864
#define Mrows (Bn*Tn)   // 32768

#define KT    32              // fp16 K per tile
#define NKT   (DT/KT)         // 152 k-tiles
#define MT    256             // M rows per CTA (gemm1)

// -------- scratch (static __device__, no allocations) --------
__device__ __half g_scores_h[(size_t)Mrows * REDn];       // 8 MB (fp16 scores + bias)
__device__ float g_xg[(size_t)Mrows * 192];               // 24 MB
__device__ float g_outF[(size_t)Mrows * Hn];              // 4 MB
__device__ float g_outB[(size_t)Mrows * Hn];              // 4 MB
__device__ __half g_Wh[(size_t)REDn * DT];                // 1.25 MB (fp16 fc0_w)
__device__ __half g_Wih_h[192 * REDn];                    // 48 KB (fp16 [wih_f;wih_b])

// ============================================================
// helpers
// ============================================================
__device__ __forceinline__ uint32_t smem_u32(const void* p) {
    uint32_t a;
    asm("{ .reg .u64 t; cvta.to.shared.u64 t, %1; cvt.u32.u64 %0, t; }" : "=r"(a) : "l"(p));
    return a;
}
__device__ __forceinline__ void cp16(uint32_t dst, const void* src) {
    asm volatile("cp.async.cg.shared.global [%0], [%1], 16;" :: "r"(dst), "l"(src) : "memory");
}
__device__ __forceinline__ void cp_commit() {
    asm volatile("cp.async.commit_group;" ::: "memory");
}
__device__ __forceinline__ void cp_wait3() {
    asm volatile("cp.async.wait_group 3;" ::: "memory");
}
__device__ __forceinline__ void cp_wait0() {
    asm volatile("cp.async.wait_group 0;" ::: "memory");
}
__device__ __forceinline__ void ldsm_x4(uint32_t* r, uint32_t addr) {
    asm volatile("ldmatrix.sync.aligned.m8n8.x4.shared.b16 {%0,%1,%2,%3}, [%4];"
                 : "=r"(r[0]), "=r"(r[1]), "=r"(r[2]), "=r"(r[3]) : "r"(addr));
}
__device__ __forceinline__ void mma16816h(float* c, const uint32_t* a, const uint32_t* b) {
    asm volatile("mma.sync.aligned.m16n8k16.row.col.f32.f16.f16.f32 "
                 "{%0,%1,%2,%3}, {%4,%5,%6,%7}, {%8,%9}, {%0,%1,%2,%3};"
                 : "+f"(c[0]), "+f"(c[1]), "+f"(c[2]), "+f"(c[3])
                 : "r"(a[0]), "r"(a[1]), "r"(a[2]), "r"(a[3]), "r"(b[0]), "r"(b[1]));
}
__device__ __forceinline__ void cvt4h(float4 v, uint32_t& h01, uint32_t& h23) {
    __half2 H0 = __floats2half2_rn(v.x, v.y);
    __half2 H1 = __floats2half2_rn(v.z, v.w);
    h01 = *reinterpret_cast<uint32_t*>(&H0);
    h23 = *reinterpret_cast<uint32_t*>(&H1);
}
// packed dual-fp32 ops (GRU)
__device__ __forceinline__ unsigned long long pack2(float x, float y) {
    unsigned long long r;
    asm("mov.b64 %0, {%1,%2};" : "=l"(r) : "f"(x), "f"(y));
    return r;
}
__device__ __forceinline__ unsigned long long ffma2(unsigned long long a,
                                                    unsigned long long b,
                                                    unsigned long long c) {
    unsigned long long d;
    asm("fma.rn.f32x2 %0, %1, %2, %3;" : "=l"(d) : "l"(a), "l"(b), "l"(c));
    return d;
}
__device__ __forceinline__ unsigned long long fadd2(unsigned long long a,
                                                    unsigned long long b) {
    unsigned long long d;
    asm("add.rn.f32x2 %0, %1, %2;" : "=l"(d) : "l"(a), "l"(b));
    return d;
}
__device__ __forceinline__ float2 unpack2(unsigned long long v) {
    float2 f;
    asm("mov.b64 {%0,%1}, %2;" : "=f"(f.x), "=f"(f.y) : "l"(v));
    return f;
}
__device__ __forceinline__ float rcp_fast(float x) {
    float y;
    asm("rcp.approx.f32 %0, %1;" : "=f"(y) : "f"(x));
    return y;
}
__device__ __forceinline__ float sigmoid_fast(float x) {
    return rcp_fast(1.f + __expf(-x));
}
__device__ __forceinline__ float tanh_fast(float x) {
    return __fmaf_rn(2.f, rcp_fast(1.f + __expf(-2.f * x)), -1.f);
}

// ============================================================
// Kernel 0a: convert fc0_w to fp16
// ============================================================
__global__ void __launch_bounds__(256) k_prep_w(const float* __restrict__ W) {
    int i = blockIdx.x * 256 + threadIdx.x;
    if (i < REDn * DT) g_Wh[i] = __float2half_rn(W[i]);
}
// Kernel 0b: convert [wih_f; wih_b] to fp16
__global__ void __launch_bounds__(256) k_prep_wih(const float* __restrict__ wf,
                                                  const float* __restrict__ wb) {
    int i = blockIdx.x * 256 + threadIdx.x;
    if (i < 192 * REDn) {
        int r = i >> 7, c = i & 127;
        float v = (r < 96) ? wf[r * REDn + c] : wb[(r - 96) * REDn + c];
        g_Wih_h[i] = __float2half_rn(v);
    }
}

// ============================================================
// Kernel 1: mma.sync fp16 GEMM1 (R14 proven). Output: fp16 scores+bias.
// ============================================================
#define SM_ABF    0u
#define SM_WRING  20480u
#define WSTG      10240u
#define DYN_SMEM  (20480 + 4*10240 + 1024)   // 62464

__global__ void __launch_bounds__(512, 1) k_gemm1_mma(
    const float* __restrict__ content, const float* __restrict__ distort,
    const float* __restrict__ motion,  const float* __restrict__ bias,
    const int* __restrict__ inputLength)
{
    const int m0 = blockIdx.x * MT;
    {
        const int vlen = inputLength[m0 >> 9] - 9;
        if ((m0 & 511) >= vlen) return;
    }

    extern __shared__ char dynsmem[];
    __shared__ float s_bias[128];

    const int tid = threadIdx.x;
    const int wid = tid >> 5;
    const int lid = tid & 31;
    const int wm  = wid & 3;
    const int wn  = wid >> 2;

    const uint32_t raw  = smem_u32(dynsmem);
    const uint32_t base = (raw + 1023u) & ~1023u;
    char* sm = dynsmem + (base - raw);

    if (tid < 128) s_bias[tid] = bias[tid];

    const int hrow = tid >> 2;
    const int jw   = tid & 3;
    const int ar0 = tid >> 3;
    const int aj  = tid & 7;

    const uint32_t aoff = (uint32_t)((wm * 64 + (lid & 15)) * 80 + ((lid >> 4) << 4));
    const int g3 = lid >> 3;
    const uint32_t brow_off = (uint32_t)(((g3 >> 1) << 3) + (lid & 7));
    const uint32_t bk_off   = (uint32_t)((g3 & 1) * 16);

    float acc[4][4][4];
#pragma unroll
    for (int i = 0; i < 4; i++)
#pragma unroll
        for (int j = 0; j < 4; j++)
#pragma unroll
            for (int k = 0; k < 4; k++) acc[i][j][k] = 0.f;

    float4 areg[4];

    auto load_a = [&](int c) {
        if (c < NKT) {
            const int kt = c * KT;
            const float* asrc; int astr, koff;
            if (kt < DC)           { asrc = content; astr = DC; koff = kt; }
            else if (kt < DC + DD) { asrc = distort; astr = DD; koff = kt - DC; }
            else                   { asrc = motion;  astr = DM; koff = kt - DC - DD; }
#pragma unroll
            for (int i = 0; i < 4; ++i) {
                int r = ar0 + i * 64;
                areg[i] = *reinterpret_cast<const float4*>(
                    asrc + (size_t)(m0 + r) * astr + koff + aj * 4);
            }
        }
    };

    auto issue_w = [&](int c) {
        if (c < NKT) {
            const int kt = c * KT;
            const uint32_t wb = base + SM_WRING + (uint32_t)(c & 3) * WSTG;
            cp16(wb + (uint32_t)(hrow * 80 + jw * 16),
                 (const char*)g_Wh + ((size_t)hrow * DT + kt) * 2 + jw * 16);
        }
        cp_commit();
    };

    load_a(0);
    issue_w(0);
    issue_w(1);
    issue_w(2);

    for (int c = 0; c < NKT; ++c) {
        __syncthreads();

#pragma unroll
        for (int i = 0; i < 4; ++i) {
            int r = ar0 + i * 64;
            uint32_t h01, h23;
            cvt4h(areg[i], h01, h23);
            *reinterpret_cast<uint2*>(sm + SM_ABF + r * 80 + aj * 8) = make_uint2(h01, h23);
        }
        load_a(c + 1);
        issue_w(c + 3);
        cp_wait3();
        __syncthreads();

        const uint32_t wbh = base + SM_WRING + (uint32_t)(c & 3) * WSTG;
#pragma unroll
        for (int ks = 0; ks < 2; ks++) {
            const uint32_t akb = base + SM_ABF + aoff + (uint32_t)(ks * 32);
            uint32_t ah[4][4], bb[4][2];
#pragma unroll
            for (int mf = 0; mf < 4; mf++) ldsm_x4(ah[mf], akb + (uint32_t)(mf * 1280));
#pragma unroll
            for (int p = 0; p < 2; p++) {
                uint32_t r4[4];
                uint32_t addr = wbh + (uint32_t)((wn * 32 + p * 16 + brow_off) * 80)
                                    + bk_off + (uint32_t)(ks * 32);
                ldsm_x4(r4, addr);
                bb[2*p][0] = r4[0]; bb[2*p][1] = r4[1];
                bb[2*p+1][0] = r4[2]; bb[2*p+1][1] = r4[3];
            }
#pragma unroll
            for (int mf = 0; mf < 4; mf++)
#pragma unroll
                for (int nf = 0; nf < 4; nf++) mma16816h(acc[mf][nf], ah[mf], bb[nf]);
        }
    }

    // epilogue: scores + bias -> fp16 gmem
    {
        const int gq = lid >> 2;
        const int t4 = lid & 3;
#pragma unroll
        for (int mf = 0; mf < 4; mf++) {
            const int row0 = m0 + wm * 64 + mf * 16 + gq;
#pragma unroll
            for (int nf = 0; nf < 4; nf++) {
                const int col = wn * 32 + nf * 8 + 2 * t4;
                const float b0 = s_bias[col], b1 = s_bias[col + 1];
                __half2 v0 = __floats2half2_rn(acc[mf][nf][0] + b0, acc[mf][nf][1] + b1);
                __half2 v1 = __floats2half2_rn(acc[mf][nf][2] + b0, acc[mf][nf][3] + b1);
                *reinterpret_cast<uint32_t*>(
                    (char*)g_scores_h + ((size_t)row0 * REDn + col) * 2) =
                    *reinterpret_cast<uint32_t*>(&v0);
                *reinterpret_cast<uint32_t*>(
                    (char*)g_scores_h + ((size_t)(row0 + 8) * REDn + col) * 2) =
                    *reinterpret_cast<uint32_t*>(&v1);
            }
        }
    }
}

// ============================================================
// Kernel 2: fp16 mma GEMM2: xg[M,192] = scores_h @ wih_h^T + bih.
// MT=128 rows/CTA, 16 warps (4m x 4n), warp tile 32x48. K=128 as 4
// chunks in the proven pitch-80 layout; all smem preloaded once.
//
// SMEM: A [4 chunks][128 rows][80B] = 40960 ; W [4][192][80B] = 61440
// ============================================================
#define G2_A     0u
#define G2_ACH   10240u
#define G2_W     40960u
#define G2_WCH   15360u
#define G2_SMEM  (40960 + 61440 + 1024)   // 103424

__global__ void __launch_bounds__(512, 1) k_gemm2h(
    const float* __restrict__ bih_f, const float* __restrict__ bih_b,
    const int* __restrict__ inputLength)
{
    const int m0 = blockIdx.x * 128;
    {
        const int vlen = inputLength[m0 >> 9] - 9;
        if ((m0 & 511) >= vlen) return;
    }

    extern __shared__ char dynsmem[];
    __shared__ float s_bih[192];

    const int tid = threadIdx.x;
    const int wid = tid >> 5;
    const int lid = tid & 31;
    const int wm  = wid & 3;     // 4 m-warps x 32 rows
    const int wn  = wid >> 2;    // 4 n-warps x 48 cols

    const uint32_t raw  = smem_u32(dynsmem);
    const uint32_t base = (raw + 1023u) & ~1023u;
    char* sm = dynsmem + (base - raw);
    (void)sm;

    if (tid < 192) s_bih[tid] = (tid < 96) ? bih_f[tid] : bih_b[tid - 96];

    // ---- load A (scores fp16) : 2048 cp16, 4 per thread ----
#pragma unroll
    for (int i = 0; i < 4; ++i) {
        int idx = i * 512 + tid;
        int kc = idx >> 9;          // 0..3
        int r  = (idx >> 2) & 127;
        int j  = idx & 3;
        cp16(base + G2_A + (uint32_t)(kc * G2_ACH + r * 80 + j * 16),
             (const char*)g_scores_h + ((size_t)(m0 + r) * REDn + kc * 32 + j * 8) * 2);
    }
    // ---- load W (wih fp16) : 3072 cp16, 6 per thread ----
#pragma unroll
    for (int i = 0; i < 6; ++i) {
        int idx = i * 512 + tid;    // idx = r*16 + kc*4 + j
        int r  = idx >> 4;          // 0..191
        int kc = (idx >> 2) & 3;
        int j  = idx & 3;
        cp16(base + G2_W + (uint32_t)(kc * G2_WCH + r * 80 + j * 16),
             (const char*)g_Wih_h + ((size_t)r * REDn + kc * 32 + j * 8) * 2);
    }
    cp_commit();
    cp_wait0();
    __syncthreads();

    const uint32_t aoff = (uint32_t)((wm * 32 + (lid & 15)) * 80 + ((lid >> 4) << 4));
    const int g3 = lid >> 3;
    const uint32_t brow_off = (uint32_t)(((g3 >> 1) << 3) + (lid & 7));
    const uint32_t bk_off   = (uint32_t)((g3 & 1) * 16);

    float acc[2][6][4];
#pragma unroll
    for (int i = 0; i < 2; i++)
#pragma unroll
        for (int j = 0; j < 6; j++)
#pragma unroll
            for (int k = 0; k < 4; k++) acc[i][j][k] = 0.f;

#pragma unroll
    for (int kc = 0; kc < 4; ++kc) {
#pragma unroll
        for (int ks = 0; ks < 2; ks++) {
            const uint32_t akb = base + G2_A + (uint32_t)(kc * G2_ACH) + aoff
                               + (uint32_t)(ks * 32);
            uint32_t ah[2][4], bb[6][2];
#pragma unroll
            for (int mf = 0; mf < 2; mf++) ldsm_x4(ah[mf], akb + (uint32_t)(mf * 1280));
#pragma unroll
            for (int p = 0; p < 3; p++) {
                uint32_t r4[4];
                uint32_t addr = base + G2_W + (uint32_t)(kc * G2_WCH)
                              + (uint32_t)((wn * 48 + p * 16 + brow_off) * 80)
                              + bk_off + (uint32_t)(ks * 32);
                ldsm_x4(r4, addr);
                bb[2*p][0] = r4[0]; bb[2*p][1] = r4[1];
                bb[2*p+1][0] = r4[2]; bb[2*p+1][1] = r4[3];
            }
#pragma unroll
            for (int mf = 0; mf < 2; mf++)
#pragma unroll
                for (int nf = 0; nf < 6; nf++) mma16816h(acc[mf][nf], ah[mf], bb[nf]);
        }
    }

    {
        const int gq = lid >> 2;
        const int t4 = lid & 3;
#pragma unroll
        for (int mf = 0; mf < 2; mf++) {
            const int row0 = m0 + wm * 32 + mf * 16 + gq;
#pragma unroll
            for (int nf = 0; nf < 6; nf++) {
                const int col = wn * 48 + nf * 8 + 2 * t4;   // 0..190
                const float b0 = s_bih[col], b1 = s_bih[col + 1];
                float* p0 = g_xg + (size_t)row0 * 192 + col;
                float* p1 = g_xg + (size_t)(row0 + 8) * 192 + col;
                *reinterpret_cast<float2*>(p0) =
                    make_float2(acc[mf][nf][0] + b0, acc[mf][nf][1] + b1);
                *reinterpret_cast<float2*>(p1) =
                    make_float2(acc[mf][nf][2] + b0, acc[mf][nf][3] + b1);
            }
        }
    }
}

// ============================================================
// Kernel 3: masked GRU — one warp per (batch, direction), loop to vlen.
// ============================================================
__global__ void __launch_bounds__(32) k_gru(
    const int*   __restrict__ inputLength,
    const float* __restrict__ whh_f, const float* __restrict__ whh_b,
    const float* __restrict__ bhh_f, const float* __restrict__ bhh_b)
{
    const int b   = blockIdx.x;
    const int dir = blockIdx.y;
    const int j   = threadIdx.x;

    const float* whh = dir ? whh_b : whh_f;
    const float* bhh = dir ? bhh_b : bhh_f;

    unsigned long long wr[16], wz[16], wn2[16];
    const float2* wrp = reinterpret_cast<const float2*>(whh + j * 32);
    const float2* wzp = reinterpret_cast<const float2*>(whh + (32 + j) * 32);
    const float2* wnp = reinterpret_cast<const float2*>(whh + (64 + j) * 32);
#pragma unroll
    for (int i = 0; i < 16; i++) {
        float2 a = wrp[i], cz = wzp[i], d = wnp[i];
        wr[i]  = pack2(a.x, a.y);
        wz[i]  = pack2(cz.x, cz.y);
        wn2[i] = pack2(d.x, d.y);
    }
    const float br = bhh[j], bz = bhh[32 + j], bn = bhh[64 + j];

    __shared__ __align__(16) float sh[2][32];

    const int vlen = inputLength[b] - 9;
    float* outp = (dir ? g_outB : g_outF) + (size_t)b * Tn * Hn + j;
    const float* xgbase = g_xg + (size_t)b * Tn * 192 + dir * 96;

    float xr0,xz0,xn0, xr1,xz1,xn1, xr2,xz2,xn2, xr3,xz3,xn3, xr4,xz4,xn4, xr5,xz5,xn5;
#define PRELOAD(K, XR, XZ, XN)                                                \
    {                                                                         \
        const float* x = xgbase + (size_t)(dir ? (vlen - 1 - (K)) : (K)) * 192; \
        XR = x[j]; XZ = x[32 + j]; XN = x[64 + j];                            \
    }
    PRELOAD(0, xr0, xz0, xn0)
    PRELOAD(1, xr1, xz1, xn1)
    PRELOAD(2, xr2, xz2, xn2)
    PRELOAD(3, xr3, xz3, xn3)
    PRELOAD(4, xr4, xz4, xn4)
    PRELOAD(5, xr5, xz5, xn5)
#undef PRELOAD

    float h = 0.f;
    int s = 0;

#define GRU_STEP(XR, XZ, XN)                                                  \
    {                                                                         \
        const float cxr = XR, cxz = XZ, cxn = XN;                             \
        const int sp = s + 6;                                                 \
        if (sp < vlen) {                                                      \
            const float* x = xgbase + (size_t)(dir ? (vlen - 1 - sp) : sp) * 192; \
            XR = x[j]; XZ = x[32 + j]; XN = x[64 + j];                        \
        }                                                                     \
        sh[s & 1][j] = h;                                                     \
        __syncwarp();                                                         \
        const unsigned long long* hp =                                        \
            reinterpret_cast<const unsigned long long*>(&sh[s & 1][0]);       \
        unsigned long long ar0 = 0ull, ar1 = 0ull;                            \
        unsigned long long az0 = 0ull, az1 = 0ull;                            \
        unsigned long long an0 = 0ull, an1 = 0ull;                            \
        _Pragma("unroll")                                                     \
        for (int i = 0; i < 16; i += 2) {                                     \
            unsigned long long hv0 = hp[i];                                   \
            unsigned long long hv1 = hp[i + 1];                               \
            ar0 = ffma2(hv0, wr[i],      ar0);                                \
            ar1 = ffma2(hv1, wr[i + 1],  ar1);                                \
            az0 = ffma2(hv0, wz[i],      az0);                                \
            az1 = ffma2(hv1, wz[i + 1],  az1);                                \
            an0 = ffma2(hv0, wn2[i],     an0);                                \
            an1 = ffma2(hv1, wn2[i + 1], an1);                                \
        }                                                                     \
        float2 fr = unpack2(fadd2(ar0, ar1));                                 \
        float2 fz = unpack2(fadd2(az0, az1));                                 \
        float2 fn = unpack2(fadd2(an0, an1));                                 \
        float hgr = fr.x + fr.y + br;                                         \
        float hgz = fz.x + fz.y + bz;                                         \
        float hgn = fn.x + fn.y + bn;                                         \
        float r  = sigmoid_fast(cxr + hgr);                                   \
        float z  = sigmoid_fast(cxz + hgz);                                   \
        float nn = tanh_fast(__fmaf_rn(r, hgn, cxn));                         \
        h = __fmaf_rn(z, h - nn, nn);                                         \
        int tout = dir ? (vlen - 1 - s) : s;                                  \
        outp[(size_t)tout * Hn] = h;                                          \
        s++;                                                                  \
    }

    while (s + 6 <= vlen) {
        GRU_STEP(xr0, xz0, xn0)
        GRU_STEP(xr1, xz1, xn1)
        GRU_STEP(xr2, xz2, xn2)
        GRU_STEP(xr3, xz3, xn3)
        GRU_STEP(xr4, xz4, xn4)
        GRU_STEP(xr5, xz5, xn5)
    }
    if (s < vlen) GRU_STEP(xr0, xz0, xn0)
    if (s < vlen) GRU_STEP(xr1, xz1, xn1)
    if (s < vlen) GRU_STEP(xr2, xz2, xn2)
    if (s < vlen) GRU_STEP(xr3, xz3, xn3)
    if (s < vlen) GRU_STEP(xr4, xz4, xn4)
#undef GRU_STEP
}

// ============================================================
// Kernel 4: q projection + MLP + argmax-selected TP score.
// ============================================================
__global__ void __launch_bounds__(512) k_final(
    const int*   __restrict__ inputLength,
    const float* __restrict__ qw,  const float* __restrict__ qb,
    const float* __restrict__ m1w, const float* __restrict__ m1b,
    const float* __restrict__ m2w, const float* __restrict__ m2b,
    float* __restrict__ out)
{
    const int b = blockIdx.x;
    const int t = threadIdx.x;
    __shared__ float sq[512];
    __shared__ float sh1[32];
    __shared__ int   s_tau;
    __shared__ float wsum[16];

    const int vlen = inputLength[b] - 9;

    float qv = 0.f;
    if (t < vlen) {
        const float* of = g_outF + ((size_t)b * Tn + t) * Hn;
        const float* ob = g_outB + ((size_t)b * Tn + t) * Hn;
        float a = qb[0];
#pragma unroll
        for (int jj = 0; jj < 32; jj++) a += of[jj] * qw[jj] + ob[jj] * qw[32 + jj];
        qv = a;
    }
    sq[t] = qv;
    __syncthreads();

    if (t < 32) {
        const float* lf = g_outF + ((size_t)b * Tn + (vlen - 1)) * Hn;
        const float* lb = g_outB + ((size_t)b * Tn) * Hn;
        float a = m1b[t];
#pragma unroll
        for (int jj = 0; jj < 32; jj++) a += lf[jj] * m1w[t * 64 + jj] + lb[jj] * m1w[t * 64 + 32 + jj];
        sh1[t] = fmaxf(a, 0.f);
    }
    __syncthreads();
    if (t == 0) {
        float best = -3.0e38f; int bi = 0;
#pragma unroll
        for (int c = 0; c < 5; c++) {
            float v = m2b[c];
#pragma unroll
            for (int o = 0; o < 32; o++) v += sh1[o] * m2w[c * 32 + o];
            if (v > best) { best = v; bi = c; }
        }
        s_tau = 8 + 2 * bi;
    }
    __syncthreads();

    const int tau = s_tau;
    float pm = 0.f;
    if (t < vlen) {
        float l = 3.0e38f;
        for (int k = 0; k < tau; k++) {
            int idx = t - k;
            float v = (idx >= 0) ? sq[idx] : 3.0e38f;
            l = fminf(l, v);
        }
        float msum = 0.f, nsum = 0.f;
        for (int k = 0; k < tau; k++) {
            int idx = t + k;
            if (idx < vlen) {
                float w = __expf(-sq[idx]);
                nsum += w;
                msum += sq[idx] * w;
            }
        }
        float ratio = (nsum > 0.f) ? (msum / nsum) : 0.f;
        pm = 0.5f * (ratio + l);
    }
    float v = pm;
#pragma unroll
    for (int o = 16; o > 0; o >>= 1) v += __shfl_down_sync(0xffffffffu, v, o);
    if ((t & 31) == 0) wsum[t >> 5] = v;
    __syncthreads();
    if (t == 0) {
        float s = 0.f;
#pragma unroll
        for (int w = 0; w < 16; w++) s += wsum[w];
        out[b] = s / (float)vlen;
    }
}

// ============================================================
extern "C" void kernel_launch(void* const* d_in, const int* in_sizes, int n_in,
                              void* d_out, int out_size) {
    (void)in_sizes; (void)n_in; (void)out_size;
    const float* motion   = (const float*)d_in[0];
    const float* content  = (const float*)d_in[1];
    const float* distort  = (const float*)d_in[2];
    const int*   inlen    = (const int*)  d_in[3];
    const float* fc0w     = (const float*)d_in[4];
    const float* fc0b     = (const float*)d_in[5];
    const float* wih_f    = (const float*)d_in[6];
    const float* whh_f    = (const float*)d_in[7];
    const float* bih_f    = (const float*)d_in[8];
    const float* bhh_f    = (const float*)d_in[9];
    const float* wih_b    = (const float*)d_in[10];
    const float* whh_b    = (const float*)d_in[11];
    const float* bih_b    = (const float*)d_in[12];
    const float* bhh_b    = (const float*)d_in[13];
    const float* qw       = (const float*)d_in[14];
    const float* qb       = (const float*)d_in[15];
    const float* m1w      = (const float*)d_in[16];
    const float* m1b      = (const float*)d_in[17];
    const float* m2w      = (const float*)d_in[18];
    const float* m2b      = (const float*)d_in[19];
    float* out = (float*)d_out;

    cudaFuncSetAttribute(k_gemm1_mma, cudaFuncAttributeMaxDynamicSharedMemorySize, DYN_SMEM);
    cudaFuncSetAttribute(k_gemm2h, cudaFuncAttributeMaxDynamicSharedMemorySize, G2_SMEM);

    k_prep_w<<<(REDn * DT + 255) / 256, 256>>>(fc0w);
    k_prep_wih<<<(192 * REDn + 255) / 256, 256>>>(wih_f, wih_b);
    k_gemm1_mma<<<Mrows / MT, 512, DYN_SMEM>>>(content, distort, motion, fc0b, inlen);
    k_gemm2h<<<Mrows / 128, 512, G2_SMEM>>>(bih_f, bih_b, inlen);
    k_gru<<<dim3(Bn, 2), 32>>>(inlen, whh_f, whh_b, bhh_f, bhh_b);
    k_final<<<Bn, 512>>>(inlen, qw, qb, m1w, m1b, m2w, m2b, out);
}